// round 13
// baseline (speedup 1.0000x reference)
#include <cuda_runtime.h>
#include <cuda_bf16.h>
#include <cstdint>

typedef unsigned long long ull;
typedef unsigned int u32;
typedef unsigned short u16;

#define B_   2
#define L_   110592
#define C_   64
#define DI_  128
#define NCH  1728
#define NTIL (B_ * NCH)         // 3456
#define EPS_ 1e-3f

// ---- k1a smem layout v3 (bytes) ----
#define P1_W1H 0
#define P1_W1L 32768
#define P1_XB  65536
#define P1_A   82944
#define P1_XS  132096
#define P1_XCH 167936
#define P1_XCL 184320
#define P1_SMEM 200704
// ---- kb smem layout (bytes) ----
#define KB_BH   0
#define KB_BL   65536
#define KB_A    131072          // 2 x 32KB
#define KB_BDT  196608
#define KB_SUMS 197120
#define KB_SMEM 197632
// ---- k3 smem layout (bytes) ----
#define S3_W3H 0
#define S3_W3L 16384
#define S3_YH  32768
#define S3_YL  49152
#define S3_OFF 65536
#define S3_MID 66048
#define S3_RS  66560
#define S3_RQ  67072
#define S3_GB  67584
#define S3_SMEM 68096

// ---------------- global scratch ----------------
__device__ float g_u[(size_t)B_ * L_ * DI_];
__device__ float g_res[(size_t)B_ * L_ * DI_];
__device__ float g_sums[NTIL * DI_];
__device__ float g_offs[NTIL * DI_];
__device__ uint4 g_xch4[(size_t)NTIL * 1024];
__device__ uint4 g_xcl4[(size_t)NTIL * 1024];
__device__ uint4 g_Bh4[4096];
__device__ uint4 g_Bl4[4096];
__device__ uint4 g_W1h4[2048];
__device__ uint4 g_W1l4[2048];
__device__ uint4 g_W3h4[1024];
__device__ uint4 g_W3l4[1024];

// ---------------- helpers ----------------
__device__ __forceinline__ float softplus_f(float v) {
    return (v > 10.f) ? v : __logf(1.f + __expf(v));
}
__device__ __forceinline__ u32 smem_u32(const void* p) {
    u32 a; asm("{ .reg .u64 t; cvta.to.shared.u64 t, %1; cvt.u32.u64 %0, t; }"
               : "=r"(a) : "l"(p));
    return a;
}
__device__ __forceinline__ void mma_bf16(float& d0, float& d1, float& d2, float& d3,
                                         u32 a0, u32 a1, u32 a2, u32 a3,
                                         u32 b0, u32 b1) {
    asm volatile("mma.sync.aligned.m16n8k16.row.col.f32.bf16.bf16.f32 "
                 "{%0,%1,%2,%3}, {%4,%5,%6,%7}, {%8,%9}, {%0,%1,%2,%3};"
                 : "+f"(d0), "+f"(d1), "+f"(d2), "+f"(d3)
                 : "r"(a0), "r"(a1), "r"(a2), "r"(a3), "r"(b0), "r"(b1));
}
__device__ __forceinline__ void ldmatrix_x4(u32& r0, u32& r1, u32& r2, u32& r3, u32 addr) {
    asm volatile("ldmatrix.sync.aligned.m8n8.x4.shared.b16 {%0,%1,%2,%3}, [%4];"
                 : "=r"(r0), "=r"(r1), "=r"(r2), "=r"(r3) : "r"(addr));
}
__device__ __forceinline__ void ldmatrix_x2t(u32& r0, u32& r1, u32 addr) {
    asm volatile("ldmatrix.sync.aligned.m8n8.x2.trans.shared.b16 {%0,%1}, [%2];"
                 : "=r"(r0), "=r"(r1) : "r"(addr));
}
#define CP_ASYNC16(dst, src) \
    asm volatile("cp.async.cg.shared.global [%0], [%1], 16;" :: "r"(dst), "l"(src))
#define CP_COMMIT() asm volatile("cp.async.commit_group;")
#define CP_WAIT(n)  asm volatile("cp.async.wait_group %0;" :: "n"(n))

// Truncation split: v = hi + lo EXACTLY.
__device__ __forceinline__ void bf16_split(float v, u16& h, u16& l) {
    u32 bits = __float_as_uint(v);
    h = (u16)(bits >> 16);
    float hf = __uint_as_float(bits & 0xFFFF0000u);
    __nv_bfloat16 lb = __float2bfloat16(v - hf);
    l = *reinterpret_cast<u16*>(&lb);
}

// =====================================================================
// prep kernels (2 launches; profiled global launch idx 3 == kb)
// =====================================================================
__global__ void k_prep_w2(const float* __restrict__ W_x,
                          const float* __restrict__ W_dt)
{
    u16* bh = reinterpret_cast<u16*>(g_Bh4);
    u16* bl = reinterpret_cast<u16*>(g_Bl4);
    int idx = blockIdx.x * 256 + threadIdx.x;
    for (int i = idx; i < 128 * 256; i += gridDim.x * 256) {
        int k = i >> 8, n = i & 255;
        float w = (n < 128) ? W_x[(size_t)k * 144 + n] : W_dt[(size_t)k * 128 + (n - 128)];
        u16 h, l; bf16_split(w, h, l);
        u32 off = (u32)k * 512 + ((((n >> 3) ^ (k & 7))) << 4) + (n & 7) * 2;
        bh[off >> 1] = h; bl[off >> 1] = l;
    }
}
__global__ void k_prep_w13(const float* __restrict__ W_in,
                           const float* __restrict__ W_out)
{
    u16* wh = reinterpret_cast<u16*>(g_W1h4);
    u16* wl = reinterpret_cast<u16*>(g_W1l4);
    u16* oh = reinterpret_cast<u16*>(g_W3h4);
    u16* ol = reinterpret_cast<u16*>(g_W3l4);
    int idx = blockIdx.x * 256 + threadIdx.x;
    for (int i = idx; i < 64 * 256; i += gridDim.x * 256) {
        int k = i >> 8, n = i & 255;
        float w = W_in[(size_t)k * 256 + n];
        u16 h, l; bf16_split(w, h, l);
        u32 off = (u32)k * 512 + ((((n >> 3) ^ (k & 7))) << 4) + (n & 7) * 2;
        wh[off >> 1] = h; wl[off >> 1] = l;
    }
    for (int i = idx; i < 128 * 64; i += gridDim.x * 256) {
        int k = i >> 6, n = i & 63;
        float w = W_out[(size_t)k * 64 + n];
        u16 h, l; bf16_split(w, h, l);
        u32 off = (u32)k * 128 + ((((n >> 3) ^ (k & 7))) << 4) + (n & 7) * 2;
        oh[off >> 1] = h; ol[off >> 1] = l;
    }
}

// =====================================================================
// k1a v3: PERSISTENT (identical to R10)
// =====================================================================
__global__ __launch_bounds__(512, 1)
void k1a_kernel(const float* __restrict__ x,
                const float* __restrict__ conv_w,
                const float* __restrict__ conv_b)
{
    extern __shared__ char sm[];
    const u32 smb = smem_u32(sm);
    float* s_xs = reinterpret_cast<float*>(sm + P1_XS);

    const int tid = threadIdx.x;

    {
        uint4* dh = reinterpret_cast<uint4*>(sm + P1_W1H);
        uint4* dl = reinterpret_cast<uint4*>(sm + P1_W1L);
        for (int i = tid; i < 2048; i += 512) { dh[i] = g_W1h4[i]; dl[i] = g_W1l4[i]; }
    }
    const float cw0 = conv_w[0 * 128 + (tid & 127)];
    const float cw1 = conv_w[1 * 128 + (tid & 127)];
    const float cw2 = conv_w[2 * 128 + (tid & 127)];
    const float cw3 = conv_w[3 * 128 + (tid & 127)];
    const float cb  = conv_b[tid & 127];

    auto prefetch = [&](int tile) {
        const int b = tile / NCH;
        const int l0 = (tile - b * NCH) * 64;
        const long base = (long)b * L_ + l0 - 1;
        for (int i = tid; i < 67 * 16; i += 512) {
            int r = i >> 4, q = i & 15;
            long gl = base + r;
            if (gl < 0) gl = 0;
            if (gl > (long)B_ * L_ - 1) gl = (long)B_ * L_ - 1;
            CP_ASYNC16(smb + P1_XB + (u32)(r * 64 + q * 4) * 4, x + gl * C_ + q * 4);
        }
    };
    auto convert = [&](int tile, int abuf) {
        const int b = tile / NCH;
        const int l0 = (tile - b * NCH) * 64;
        const float* xb = reinterpret_cast<const float*>(sm + P1_XB);
        const u32 aOff = (u32)P1_A + (u32)abuf * 24576;
        for (int i = tid; i < 67 * 16; i += 512) {
            int r = i >> 4, q = i & 15;
            int l = l0 - 1 + r;
            float4 v = *reinterpret_cast<const float4*>(xb + r * 64 + q * 4);
            if (l < 0 || l >= L_) v = make_float4(0.f, 0.f, 0.f, 0.f);
            u16 h0,lo0,h1,lo1,h2,lo2,h3,lo3;
            bf16_split(v.x, h0, lo0); bf16_split(v.y, h1, lo1);
            bf16_split(v.z, h2, lo2); bf16_split(v.w, h3, lo3);
            ull hv = (ull)h0 | ((ull)h1 << 16) | ((ull)h2 << 32) | ((ull)h3 << 48);
            ull lv = (ull)lo0 | ((ull)lo1 << 16) | ((ull)lo2 << 32) | ((ull)lo3 << 48);
            u32 off = (u32)r * 128 + ((((q >> 1) ^ (r & 7))) << 4) + (q & 1) * 8;
            *reinterpret_cast<ull*>(sm + aOff + off) = hv;
            *reinterpret_cast<ull*>(sm + aOff + 12288 + off) = lv;
        }
    };

    const int tile0 = blockIdx.x;
    if (tile0 < NTIL) {
        prefetch(tile0); CP_COMMIT(); CP_WAIT(0);
        convert(tile0, 0);
    }
    __syncthreads();

    int it = 0;
    for (int tile = tile0; tile < NTIL; tile += gridDim.x, it++) {
        const int buf = it & 1;
        const int b     = tile / NCH;
        const int chunk = tile - b * NCH;
        const int l0    = chunk * 64;
        const int nxt   = tile + gridDim.x;

        if (nxt < NTIL) { prefetch(nxt); CP_COMMIT(); }

        const int w = tid >> 5, lane = tid & 31;
        const int wm = w >> 3;
        const int wn = w & 7;

        float acc[3][4][4];
        #pragma unroll
        for (int mf = 0; mf < 3; mf++)
            #pragma unroll
            for (int nf = 0; nf < 4; nf++)
                #pragma unroll
                for (int j = 0; j < 4; j++) acc[mf][nf][j] = 0.f;

        const u32 aHb = smb + P1_A + (u32)buf * 24576;
        const u32 aLb = aHb + 12288;
        const u32 bHb = smb + P1_W1H, bLb = smb + P1_W1L;

        #pragma unroll
        for (int ks = 0; ks < 4; ks++) {
            u32 ah[3][4], al[3][4];
            #pragma unroll
            for (int mf = 0; mf < 3; mf++) {
                int row = wm * 48 + mf * 16 + (lane & 15);
                int ck  = ks * 2 + (lane >> 4);
                u32 off = (u32)row * 128 + (((ck ^ (row & 7))) << 4);
                ldmatrix_x4(ah[mf][0], ah[mf][1], ah[mf][2], ah[mf][3], aHb + off);
                ldmatrix_x4(al[mf][0], al[mf][1], al[mf][2], al[mf][3], aLb + off);
            }
            int krow = ks * 16 + (lane & 15);
            u32 krbase = (u32)krow * 512;
            int kx = krow & 7;
            #pragma unroll
            for (int nf = 0; nf < 4; nf++) {
                int n0 = wn * 32 + nf * 8;
                u32 off = krbase + ((((n0 >> 3) ^ kx)) << 4);
                u32 bh0, bh1, bl0, bl1;
                ldmatrix_x2t(bh0, bh1, bHb + off);
                ldmatrix_x2t(bl0, bl1, bLb + off);
                #pragma unroll
                for (int mf = 0; mf < 3; mf++) {
                    mma_bf16(acc[mf][nf][0], acc[mf][nf][1], acc[mf][nf][2], acc[mf][nf][3],
                             ah[mf][0], ah[mf][1], ah[mf][2], ah[mf][3], bh0, bh1);
                    mma_bf16(acc[mf][nf][0], acc[mf][nf][1], acc[mf][nf][2], acc[mf][nf][3],
                             ah[mf][0], ah[mf][1], ah[mf][2], ah[mf][3], bl0, bl1);
                    mma_bf16(acc[mf][nf][0], acc[mf][nf][1], acc[mf][nf][2], acc[mf][nf][3],
                             al[mf][0], al[mf][1], al[mf][2], al[mf][3], bh0, bh1);
                }
            }
        }

        if (nxt < NTIL) CP_WAIT(0);

        #pragma unroll
        for (int mf = 0; mf < 3; mf++) {
            const int r0 = wm * 48 + mf * 16 + (lane >> 2);
            #pragma unroll
            for (int nf = 0; nf < 4; nf++) {
                const int n = wn * 32 + nf * 8 + (lane & 3) * 2;
                if (wn < 4) {
                    if (r0 < 67)
                        *reinterpret_cast<float2*>(s_xs + r0 * 130 + n) =
                            make_float2(acc[mf][nf][0], acc[mf][nf][1]);
                    if (r0 + 8 < 67)
                        *reinterpret_cast<float2*>(s_xs + (r0 + 8) * 130 + n) =
                            make_float2(acc[mf][nf][2], acc[mf][nf][3]);
                } else {
                    const int nn = n - 128;
                    if (r0 >= 1 && r0 <= 64) {
                        float v0 = acc[mf][nf][0], v1 = acc[mf][nf][1];
                        *reinterpret_cast<float2*>(
                            g_res + ((size_t)b * L_ + l0 + r0 - 1) * DI_ + nn) =
                            make_float2(v0 / (1.f + __expf(-v0)), v1 / (1.f + __expf(-v1)));
                    }
                    const int r1 = r0 + 8;
                    if (r1 >= 1 && r1 <= 64) {
                        float v0 = acc[mf][nf][2], v1 = acc[mf][nf][3];
                        *reinterpret_cast<float2*>(
                            g_res + ((size_t)b * L_ + l0 + r1 - 1) * DI_ + nn) =
                            make_float2(v0 / (1.f + __expf(-v0)), v1 / (1.f + __expf(-v1)));
                    }
                }
            }
        }
        if (nxt < NTIL) convert(nxt, buf ^ 1);
        __syncthreads();

        {
            u16* imgh = reinterpret_cast<u16*>(sm + P1_XCH);
            u16* imgl = reinterpret_cast<u16*>(sm + P1_XCL);
            const int cch = tid & 127, qtr = tid >> 7;
            const int t0 = qtr * 16;
            float v0 = s_xs[(t0 + 0) * 130 + cch];
            float v1 = s_xs[(t0 + 1) * 130 + cch];
            float v2 = s_xs[(t0 + 2) * 130 + cch];
            #pragma unroll 4
            for (int t = t0; t < t0 + 16; t++) {
                float v3 = s_xs[(t + 3) * 130 + cch];
                float z = fmaf(cw0, v0, fmaf(cw1, v1, fmaf(cw2, v2, fmaf(cw3, v3, cb))));
                float sig = 1.f / (1.f + __expf(-z));
                float v = z * sig;
                u16 h, l; bf16_split(v, h, l);
                u32 off = (u32)t * 256 + ((((cch >> 3) ^ (t & 7))) << 4) + (cch & 7) * 2;
                imgh[off >> 1] = h; imgl[off >> 1] = l;
                v0 = v1; v1 = v2; v2 = v3;
            }
        }
        __syncthreads();

        {
            const uint4* sh = reinterpret_cast<const uint4*>(sm + P1_XCH);
            const uint4* sl = reinterpret_cast<const uint4*>(sm + P1_XCL);
            for (int i = tid; i < 1024; i += 512) {
                g_xch4[(size_t)tile * 1024 + i] = sh[i];
                g_xcl4[(size_t)tile * 1024 + i] = sl[i];
            }
        }
    }
}

// =====================================================================
// kb: persistent tensor GEMM2, 512 threads, warp tile 32x32,
//     fragment loads software-pipelined one ks ahead (reg dbl-buffer)
// =====================================================================
__global__ __launch_bounds__(512, 1)
void kb_kernel(const float* __restrict__ b_dt)
{
    extern __shared__ char sm[];
    const u32 smb = smem_u32(sm);
    float* s_bdt  = reinterpret_cast<float*>(sm + KB_BDT);
    float* s_sums = reinterpret_cast<float*>(sm + KB_SUMS);

    const int tid  = threadIdx.x;
    const int w    = tid >> 5;
    const int lane = tid & 31;
    const int wm   = w >> 3;        // 0..1 : rows [wm*32, +32)
    const int wg   = w & 7;         // 0..7 : xp cols [wg*16,+16), dt +128

    {
        uint4* dh = reinterpret_cast<uint4*>(sm + KB_BH);
        uint4* dl = reinterpret_cast<uint4*>(sm + KB_BL);
        for (int i = tid; i < 4096; i += 512) { dh[i] = g_Bh4[i]; dl[i] = g_Bl4[i]; }
    }
    if (tid < 128) { s_bdt[tid] = b_dt[tid]; s_sums[tid] = 0.f; }

    int tile0 = blockIdx.x;
    if (tile0 < NTIL) {
        u32 dh = smb + KB_A;
        const char* srcH = reinterpret_cast<const char*>(g_xch4 + (size_t)tile0 * 1024);
        const char* srcL = reinterpret_cast<const char*>(g_xcl4 + (size_t)tile0 * 1024);
        for (int i = tid; i < 1024; i += 512) {
            CP_ASYNC16(dh + i * 16,         srcH + i * 16);
            CP_ASYNC16(dh + 16384 + i * 16, srcL + i * 16);
        }
    }
    CP_COMMIT();

    int it = 0;
    for (int tile = tile0; tile < NTIL; tile += gridDim.x, it++) {
        const int buf = it & 1;
        const int nxt = tile + gridDim.x;
        if (nxt < NTIL) {
            u32 dh = smb + KB_A + (buf ^ 1) * 32768;
            const char* srcH = reinterpret_cast<const char*>(g_xch4 + (size_t)nxt * 1024);
            const char* srcL = reinterpret_cast<const char*>(g_xcl4 + (size_t)nxt * 1024);
            for (int i = tid; i < 1024; i += 512) {
                CP_ASYNC16(dh + i * 16,         srcH + i * 16);
                CP_ASYNC16(dh + 16384 + i * 16, srcL + i * 16);
            }
            CP_COMMIT();
            CP_WAIT(1);
        } else {
            CP_WAIT(0);
        }
        __syncthreads();

        const u32 aH = smb + KB_A + buf * 32768;
        const u32 aL = aH + 16384;
        const u32 bH = smb + KB_BH;
        const u32 bL = smb + KB_BL;

        float acc[2][4][4];
        #pragma unroll
        for (int mf = 0; mf < 2; mf++)
            #pragma unroll
            for (int nf = 0; nf < 4; nf++)
                #pragma unroll
                for (int j = 0; j < 4; j++) acc[mf][nf][j] = 0.f;

        // fragment double buffers: [slot][mf][hi0..3 | lo0..3], [slot][nfi][bh0,bh1,bl0,bl1]
        u32 aF[2][2][8];
        u32 bF[2][4][4];

        // prologue: load ks=0 into slot 0
        {
            const int ck = (lane >> 4);
            #pragma unroll
            for (int mf = 0; mf < 2; mf++) {
                int row = wm * 32 + mf * 16 + (lane & 15);
                u32 off = (u32)row * 256 + (((ck ^ (row & 7))) << 4);
                ldmatrix_x4(aF[0][mf][0], aF[0][mf][1], aF[0][mf][2], aF[0][mf][3], aH + off);
                ldmatrix_x4(aF[0][mf][4], aF[0][mf][5], aF[0][mf][6], aF[0][mf][7], aL + off);
            }
            const int krow = (lane & 15);
            const u32 krbase = (u32)krow * 512;
            const int kx = krow & 7;
            #pragma unroll
            for (int nfi = 0; nfi < 4; nfi++) {
                int n0 = (nfi < 2) ? (wg * 16 + nfi * 8) : (128 + wg * 16 + (nfi - 2) * 8);
                u32 off = krbase + ((((n0 >> 3) ^ kx)) << 4);
                ldmatrix_x2t(bF[0][nfi][0], bF[0][nfi][1], bH + off);
                ldmatrix_x2t(bF[0][nfi][2], bF[0][nfi][3], bL + off);
            }
        }

        #pragma unroll 1
        for (int ks = 0; ks < 8; ks++) {
            const int cur = ks & 1;
            if (ks < 7) {
                const int nk = ks + 1, slot = cur ^ 1;
                const int ck = nk * 2 + (lane >> 4);
                #pragma unroll
                for (int mf = 0; mf < 2; mf++) {
                    int row = wm * 32 + mf * 16 + (lane & 15);
                    u32 off = (u32)row * 256 + (((ck ^ (row & 7))) << 4);
                    ldmatrix_x4(aF[slot][mf][0], aF[slot][mf][1], aF[slot][mf][2], aF[slot][mf][3], aH + off);
                    ldmatrix_x4(aF[slot][mf][4], aF[slot][mf][5], aF[slot][mf][6], aF[slot][mf][7], aL + off);
                }
                const int krow = nk * 16 + (lane & 15);
                const u32 krbase = (u32)krow * 512;
                const int kx = krow & 7;
                #pragma unroll
                for (int nfi = 0; nfi < 4; nfi++) {
                    int n0 = (nfi < 2) ? (wg * 16 + nfi * 8) : (128 + wg * 16 + (nfi - 2) * 8);
                    u32 off = krbase + ((((n0 >> 3) ^ kx)) << 4);
                    ldmatrix_x2t(bF[slot][nfi][0], bF[slot][nfi][1], bH + off);
                    ldmatrix_x2t(bF[slot][nfi][2], bF[slot][nfi][3], bL + off);
                }
            }
            #pragma unroll
            for (int nfi = 0; nfi < 4; nfi++) {
                #pragma unroll
                for (int mf = 0; mf < 2; mf++) {
                    mma_bf16(acc[mf][nfi][0], acc[mf][nfi][1], acc[mf][nfi][2], acc[mf][nfi][3],
                             aF[cur][mf][0], aF[cur][mf][1], aF[cur][mf][2], aF[cur][mf][3],
                             bF[cur][nfi][0], bF[cur][nfi][1]);
                    mma_bf16(acc[mf][nfi][0], acc[mf][nfi][1], acc[mf][nfi][2], acc[mf][nfi][3],
                             aF[cur][mf][0], aF[cur][mf][1], aF[cur][mf][2], aF[cur][mf][3],
                             bF[cur][nfi][2], bF[cur][nfi][3]);
                    mma_bf16(acc[mf][nfi][0], acc[mf][nfi][1], acc[mf][nfi][2], acc[mf][nfi][3],
                             aF[cur][mf][4], aF[cur][mf][5], aF[cur][mf][6], aF[cur][mf][7],
                             bF[cur][nfi][0], bF[cur][nfi][1]);
                }
            }
        }

        #pragma unroll
        for (int mf = 0; mf < 2; mf++) {
            const int r0 = wm * 32 + mf * 16 + (lane >> 2);
            const size_t tok0 = (size_t)tile * 64 + r0;
            #pragma unroll
            for (int nfi = 0; nfi < 2; nfi++) {
                const int n = wg * 16 + nfi * 8 + (lane & 3) * 2;
                float bd0 = s_bdt[n], bd1 = s_bdt[n + 1];
                float u00 = acc[mf][nfi][0] * softplus_f(acc[mf][nfi + 2][0] + bd0);
                float u01 = acc[mf][nfi][1] * softplus_f(acc[mf][nfi + 2][1] + bd1);
                float u10 = acc[mf][nfi][2] * softplus_f(acc[mf][nfi + 2][2] + bd0);
                float u11 = acc[mf][nfi][3] * softplus_f(acc[mf][nfi + 2][3] + bd1);
                *reinterpret_cast<float2*>(g_u + tok0 * DI_ + n)       = make_float2(u00, u01);
                *reinterpret_cast<float2*>(g_u + (tok0 + 8) * DI_ + n) = make_float2(u10, u11);
                float p0 = u00 + u10, p1 = u01 + u11;
                #pragma unroll
                for (int m = 4; m <= 16; m <<= 1) {
                    p0 += __shfl_xor_sync(0xffffffffu, p0, m);
                    p1 += __shfl_xor_sync(0xffffffffu, p1, m);
                }
                if ((lane >> 2) == 0) {
                    atomicAdd(&s_sums[n], p0);
                    atomicAdd(&s_sums[n + 1], p1);
                }
            }
        }
        __syncthreads();
        if (tid < 128) {
            g_sums[(size_t)tile * DI_ + tid] = s_sums[tid];
            s_sums[tid] = 0.f;
        }
    }
}

// =====================================================================
// K2: exclusive scan of chunk sums
// =====================================================================
__global__ void k2_scan(void)
{
    const int b = blockIdx.x >> 7;
    const int c = blockIdx.x & 127;
    const int t = threadIdx.x;
    __shared__ float part[64];

    float local[27];
    float s = 0.f;
    #pragma unroll
    for (int i = 0; i < 27; i++) {
        local[i] = g_sums[(b * NCH + t * 27 + i) * DI_ + c];
        s += local[i];
    }
    part[t] = s;
    __syncthreads();
    if (t == 0) {
        float run = 0.f;
        for (int i = 0; i < 64; i++) { float v = part[i]; part[i] = run; run += v; }
    }
    __syncthreads();
    float run = part[t];
    #pragma unroll
    for (int i = 0; i < 27; i++) {
        g_offs[(b * NCH + t * 27 + i) * DI_ + c] = run;
        run += local[i];
    }
}

// =====================================================================
// K3: PERSISTENT scan -> y images ; tensor y@W_out ; +x ; LayerNorm
// =====================================================================
__global__ __launch_bounds__(256, 3)
void k3_kernel(const float* __restrict__ x,
               const float* __restrict__ gamma,
               const float* __restrict__ beta,
               float* __restrict__ out)
{
    extern __shared__ char sm[];
    const u32 smb = smem_u32(sm);
    float* s_off = reinterpret_cast<float*>(sm + S3_OFF);
    float* s_mid = reinterpret_cast<float*>(sm + S3_MID);
    float* s_rs  = reinterpret_cast<float*>(sm + S3_RS);
    float* s_rq  = reinterpret_cast<float*>(sm + S3_RQ);
    float* s_gb  = reinterpret_cast<float*>(sm + S3_GB);

    const int tid = threadIdx.x;

    {
        uint4* dh = reinterpret_cast<uint4*>(sm + S3_W3H);
        uint4* dl = reinterpret_cast<uint4*>(sm + S3_W3L);
        for (int i = tid; i < 1024; i += 256) { dh[i] = g_W3h4[i]; dl[i] = g_W3l4[i]; }
    }
    if (tid < 64)  s_gb[tid] = gamma[tid];
    else if (tid < 128) s_gb[tid] = beta[tid - 64];

    for (int tile = blockIdx.x; tile < NTIL; tile += gridDim.x) {
        const int b     = tile / NCH;
        const int chunk = tile - b * NCH;
        const int l0    = chunk * 64;

        if (tid < 128) s_off[tid] = g_offs[(size_t)tile * DI_ + tid];
        __syncthreads();

        {
            u16* imgYH = reinterpret_cast<u16*>(sm + S3_YH);
            u16* imgYL = reinterpret_cast<u16*>(sm + S3_YL);
            const int c = tid & 127, h = tid >> 7;
            const size_t base = ((size_t)b * L_ + l0 + h * 32) * DI_ + c;
            float uv[32];
            #pragma unroll
            for (int i = 0; i < 32; i++) uv[i] = g_u[base + (size_t)i * DI_];
            float ps = 0.f;
            #pragma unroll
            for (int i = 0; i < 32; i++) ps += uv[i];
            if (h == 0) s_mid[c] = ps;
            __syncthreads();
            float run = s_off[c] + (h ? s_mid[c] : 0.f);
            #pragma unroll
            for (int i = 0; i < 32; i++) {
                run += uv[i];
                float r = g_res[base + (size_t)i * DI_];
                float y = run * r;
                u16 hh, ll; bf16_split(y, hh, ll);
                int t = h * 32 + i;
                u32 off = (u32)t * 256 + ((((c >> 3) ^ (t & 7))) << 4) + (c & 7) * 2;
                imgYH[off >> 1] = hh;
                imgYL[off >> 1] = ll;
            }
        }
        __syncthreads();

        {
            const int w = tid >> 5, lane = tid & 31;
            const int wm = w >> 1;
            const int wn = w & 1;

            float acc[4][4];
            #pragma unroll
            for (int nf = 0; nf < 4; nf++)
                #pragma unroll
                for (int j = 0; j < 4; j++) acc[nf][j] = 0.f;

            const u32 yHb = smb + S3_YH, yLb = smb + S3_YL;
            const u32 wHb = smb + S3_W3H, wLb = smb + S3_W3L;

            #pragma unroll
            for (int ks = 0; ks < 8; ks++) {
                u32 ah[4], al[4];
                {
                    int row = wm * 16 + (lane & 15);
                    int ck = ks * 2 + (lane >> 4);
                    u32 off = (u32)row * 256 + (((ck ^ (row & 7))) << 4);
                    ldmatrix_x4(ah[0], ah[1], ah[2], ah[3], yHb + off);
                    ldmatrix_x4(al[0], al[1], al[2], al[3], yLb + off);
                }
                int krow = ks * 16 + (lane & 15);
                u32 krbase = (u32)krow * 128;
                int kx = krow & 7;
                #pragma unroll
                for (int nf = 0; nf < 4; nf++) {
                    int n0 = wn * 32 + nf * 8;
                    u32 off = krbase + ((((n0 >> 3) ^ kx)) << 4);
                    u32 bh0, bh1, bl0, bl1;
                    ldmatrix_x2t(bh0, bh1, wHb + off);
                    ldmatrix_x2t(bl0, bl1, wLb + off);
                    mma_bf16(acc[nf][0], acc[nf][1], acc[nf][2], acc[nf][3],
                             ah[0], ah[1], ah[2], ah[3], bh0, bh1);
                    mma_bf16(acc[nf][0], acc[nf][1], acc[nf][2], acc[nf][3],
                             ah[0], ah[1], ah[2], ah[3], bl0, bl1);
                    mma_bf16(acc[nf][0], acc[nf][1], acc[nf][2], acc[nf][3],
                             al[0], al[1], al[2], al[3], bh0, bh1);
                }
            }

            const int r0 = wm * 16 + (lane >> 2);
            const int r1 = r0 + 8;
            float z[4][4];
            float s0 = 0.f, q0 = 0.f, s1 = 0.f, q1 = 0.f;
            #pragma unroll
            for (int nf = 0; nf < 4; nf++) {
                const int c0 = wn * 32 + nf * 8 + (lane & 3) * 2;
                float2 x0 = *reinterpret_cast<const float2*>(x + ((size_t)b * L_ + l0 + r0) * C_ + c0);
                float2 x1 = *reinterpret_cast<const float2*>(x + ((size_t)b * L_ + l0 + r1) * C_ + c0);
                z[nf][0] = acc[nf][0] + x0.x;
                z[nf][1] = acc[nf][1] + x0.y;
                z[nf][2] = acc[nf][2] + x1.x;
                z[nf][3] = acc[nf][3] + x1.y;
                s0 += z[nf][0] + z[nf][1];
                q0 += z[nf][0] * z[nf][0] + z[nf][1] * z[nf][1];
                s1 += z[nf][2] + z[nf][3];
                q1 += z[nf][2] * z[nf][2] + z[nf][3] * z[nf][3];
            }
            #pragma unroll
            for (int m = 1; m <= 2; m <<= 1) {
                s0 += __shfl_xor_sync(0xffffffffu, s0, m);
                q0 += __shfl_xor_sync(0xffffffffu, q0, m);
                s1 += __shfl_xor_sync(0xffffffffu, s1, m);
                q1 += __shfl_xor_sync(0xffffffffu, q1, m);
            }
            if ((lane & 3) == 0) {
                s_rs[r0 * 2 + wn] = s0; s_rq[r0 * 2 + wn] = q0;
                s_rs[r1 * 2 + wn] = s1; s_rq[r1 * 2 + wn] = q1;
            }
            __syncthreads();

            float su0 = s_rs[r0 * 2] + s_rs[r0 * 2 + 1];
            float qu0 = s_rq[r0 * 2] + s_rq[r0 * 2 + 1];
            float su1 = s_rs[r1 * 2] + s_rs[r1 * 2 + 1];
            float qu1 = s_rq[r1 * 2] + s_rq[r1 * 2 + 1];
            float mu0 = su0 * (1.f / 64.f);
            float inv0 = rsqrtf(qu0 * (1.f / 64.f) - mu0 * mu0 + EPS_);
            float mu1 = su1 * (1.f / 64.f);
            float inv1 = rsqrtf(qu1 * (1.f / 64.f) - mu1 * mu1 + EPS_);

            #pragma unroll
            for (int nf = 0; nf < 4; nf++) {
                const int c0 = wn * 32 + nf * 8 + (lane & 3) * 2;
                float g0 = s_gb[c0], g1 = s_gb[c0 + 1];
                float be0 = s_gb[64 + c0], be1 = s_gb[64 + c0 + 1];
                *reinterpret_cast<float2*>(out + ((size_t)b * L_ + l0 + r0) * C_ + c0) =
                    make_float2(fmaf(g0, (z[nf][0] - mu0) * inv0, be0),
                                fmaf(g1, (z[nf][1] - mu0) * inv0, be1));
                *reinterpret_cast<float2*>(out + ((size_t)b * L_ + l0 + r1) * C_ + c0) =
                    make_float2(fmaf(g0, (z[nf][2] - mu1) * inv1, be0),
                                fmaf(g1, (z[nf][3] - mu1) * inv1, be1));
            }
        }
        __syncthreads();
    }
}

// =====================================================================
extern "C" void kernel_launch(void* const* d_in, const int* in_sizes, int n_in,
                              void* d_out, int out_size)
{
    (void)in_sizes; (void)n_in; (void)out_size;
    const float* x      = (const float*)d_in[0];
    const float* W_in   = (const float*)d_in[1];
    const float* conv_w = (const float*)d_in[2];
    const float* conv_b = (const float*)d_in[3];
    const float* W_x    = (const float*)d_in[4];
    const float* W_dt   = (const float*)d_in[5];
    const float* b_dt   = (const float*)d_in[6];
    const float* W_out  = (const float*)d_in[7];
    const float* gamma  = (const float*)d_in[8];
    const float* beta   = (const float*)d_in[9];
    float* out = (float*)d_out;

    cudaFuncSetAttribute(k1a_kernel, cudaFuncAttributeMaxDynamicSharedMemorySize, P1_SMEM);
    cudaFuncSetAttribute(kb_kernel,  cudaFuncAttributeMaxDynamicSharedMemorySize, KB_SMEM);
    cudaFuncSetAttribute(k3_kernel,  cudaFuncAttributeMaxDynamicSharedMemorySize, S3_SMEM);

    // launch order: profiled global launch idx 3 == kb
    k_prep_w2<<<16, 256>>>(W_x, W_dt);                      // 0
    k_prep_w13<<<16, 256>>>(W_in, W_out);                   // 1
    k1a_kernel<<<148, 512, P1_SMEM>>>(x, conv_w, conv_b);   // 2
    kb_kernel<<<148, 512, KB_SMEM>>>(b_dt);                 // 3 <- profiled
    k2_scan<<<B_ * 128, 64>>>();                            // 4
    k3_kernel<<<444, 256, S3_SMEM>>>(x, gamma, beta, out);  // 5
}

// round 14
// speedup vs baseline: 1.3931x; 1.3931x over previous
#include <cuda_runtime.h>
#include <cuda_bf16.h>
#include <cstdint>

typedef unsigned long long ull;
typedef unsigned int u32;
typedef unsigned short u16;

#define B_   2
#define L_   110592
#define C_   64
#define DI_  128
#define NCH  1728
#define NTIL (B_ * NCH)         // 3456
#define EPS_ 1e-3f

// ---- k1a smem layout v3 (bytes) ----
#define P1_W1H 0
#define P1_W1L 32768
#define P1_XB  65536
#define P1_A   82944
#define P1_XS  132096
#define P1_XCH 167936
#define P1_XCL 184320
#define P1_SMEM 200704
// ---- kb smem layout (bytes) ----
#define KB_BH   0
#define KB_BL   65536
#define KB_A    131072          // 2 x 32KB
#define KB_BDT  196608
#define KB_SUMS 197120
#define KB_SMEM 197632
// ---- k3 smem layout (bytes) ----
#define S3_W3H 0
#define S3_W3L 16384
#define S3_YH  32768
#define S3_YL  49152
#define S3_OFF 65536
#define S3_MID 66048
#define S3_RS  66560
#define S3_RQ  67072
#define S3_GB  67584
#define S3_SMEM 68096

// ---------------- global scratch ----------------
__device__ float g_u[(size_t)B_ * L_ * DI_];
__device__ float g_res[(size_t)B_ * L_ * DI_];
__device__ float g_sums[NTIL * DI_];
__device__ float g_offs[NTIL * DI_];
__device__ uint4 g_xch4[(size_t)NTIL * 1024];
__device__ uint4 g_xcl4[(size_t)NTIL * 1024];
__device__ uint4 g_Bh4[4096];
__device__ uint4 g_Bl4[4096];
__device__ uint4 g_W1h4[2048];
__device__ uint4 g_W1l4[2048];
__device__ uint4 g_W3h4[1024];
__device__ uint4 g_W3l4[1024];

// ---------------- helpers ----------------
__device__ __forceinline__ float softplus_f(float v) {
    return (v > 10.f) ? v : __logf(1.f + __expf(v));
}
__device__ __forceinline__ u32 smem_u32(const void* p) {
    u32 a; asm("{ .reg .u64 t; cvta.to.shared.u64 t, %1; cvt.u32.u64 %0, t; }"
               : "=r"(a) : "l"(p));
    return a;
}
__device__ __forceinline__ void mma_bf16(float& d0, float& d1, float& d2, float& d3,
                                         u32 a0, u32 a1, u32 a2, u32 a3,
                                         u32 b0, u32 b1) {
    asm volatile("mma.sync.aligned.m16n8k16.row.col.f32.bf16.bf16.f32 "
                 "{%0,%1,%2,%3}, {%4,%5,%6,%7}, {%8,%9}, {%0,%1,%2,%3};"
                 : "+f"(d0), "+f"(d1), "+f"(d2), "+f"(d3)
                 : "r"(a0), "r"(a1), "r"(a2), "r"(a3), "r"(b0), "r"(b1));
}
__device__ __forceinline__ void ldmatrix_x4(u32& r0, u32& r1, u32& r2, u32& r3, u32 addr) {
    asm volatile("ldmatrix.sync.aligned.m8n8.x4.shared.b16 {%0,%1,%2,%3}, [%4];"
                 : "=r"(r0), "=r"(r1), "=r"(r2), "=r"(r3) : "r"(addr));
}
__device__ __forceinline__ void ldmatrix_x2t(u32& r0, u32& r1, u32 addr) {
    asm volatile("ldmatrix.sync.aligned.m8n8.x2.trans.shared.b16 {%0,%1}, [%2];"
                 : "=r"(r0), "=r"(r1) : "r"(addr));
}
#define CP_ASYNC16(dst, src) \
    asm volatile("cp.async.cg.shared.global [%0], [%1], 16;" :: "r"(dst), "l"(src))
#define CP_COMMIT() asm volatile("cp.async.commit_group;")
#define CP_WAIT(n)  asm volatile("cp.async.wait_group %0;" :: "n"(n))

// Truncation split: v = hi + lo EXACTLY.
__device__ __forceinline__ void bf16_split(float v, u16& h, u16& l) {
    u32 bits = __float_as_uint(v);
    h = (u16)(bits >> 16);
    float hf = __uint_as_float(bits & 0xFFFF0000u);
    __nv_bfloat16 lb = __float2bfloat16(v - hf);
    l = *reinterpret_cast<u16*>(&lb);
}

// =====================================================================
// prep kernels (2 launches; profiled global launch idx 3 == kb)
// =====================================================================
__global__ void k_prep_w2(const float* __restrict__ W_x,
                          const float* __restrict__ W_dt)
{
    u16* bh = reinterpret_cast<u16*>(g_Bh4);
    u16* bl = reinterpret_cast<u16*>(g_Bl4);
    int idx = blockIdx.x * 256 + threadIdx.x;
    for (int i = idx; i < 128 * 256; i += gridDim.x * 256) {
        int k = i >> 8, n = i & 255;
        float w = (n < 128) ? W_x[(size_t)k * 144 + n] : W_dt[(size_t)k * 128 + (n - 128)];
        u16 h, l; bf16_split(w, h, l);
        u32 off = (u32)k * 512 + ((((n >> 3) ^ (k & 7))) << 4) + (n & 7) * 2;
        bh[off >> 1] = h; bl[off >> 1] = l;
    }
}
__global__ void k_prep_w13(const float* __restrict__ W_in,
                           const float* __restrict__ W_out)
{
    u16* wh = reinterpret_cast<u16*>(g_W1h4);
    u16* wl = reinterpret_cast<u16*>(g_W1l4);
    u16* oh = reinterpret_cast<u16*>(g_W3h4);
    u16* ol = reinterpret_cast<u16*>(g_W3l4);
    int idx = blockIdx.x * 256 + threadIdx.x;
    for (int i = idx; i < 64 * 256; i += gridDim.x * 256) {
        int k = i >> 8, n = i & 255;
        float w = W_in[(size_t)k * 256 + n];
        u16 h, l; bf16_split(w, h, l);
        u32 off = (u32)k * 512 + ((((n >> 3) ^ (k & 7))) << 4) + (n & 7) * 2;
        wh[off >> 1] = h; wl[off >> 1] = l;
    }
    for (int i = idx; i < 128 * 64; i += gridDim.x * 256) {
        int k = i >> 6, n = i & 63;
        float w = W_out[(size_t)k * 64 + n];
        u16 h, l; bf16_split(w, h, l);
        u32 off = (u32)k * 128 + ((((n >> 3) ^ (k & 7))) << 4) + (n & 7) * 2;
        oh[off >> 1] = h; ol[off >> 1] = l;
    }
}

// =====================================================================
// k1a v3: PERSISTENT (identical to R10)
// =====================================================================
__global__ __launch_bounds__(512, 1)
void k1a_kernel(const float* __restrict__ x,
                const float* __restrict__ conv_w,
                const float* __restrict__ conv_b)
{
    extern __shared__ char sm[];
    const u32 smb = smem_u32(sm);
    float* s_xs = reinterpret_cast<float*>(sm + P1_XS);

    const int tid = threadIdx.x;

    {
        uint4* dh = reinterpret_cast<uint4*>(sm + P1_W1H);
        uint4* dl = reinterpret_cast<uint4*>(sm + P1_W1L);
        for (int i = tid; i < 2048; i += 512) { dh[i] = g_W1h4[i]; dl[i] = g_W1l4[i]; }
    }
    const float cw0 = conv_w[0 * 128 + (tid & 127)];
    const float cw1 = conv_w[1 * 128 + (tid & 127)];
    const float cw2 = conv_w[2 * 128 + (tid & 127)];
    const float cw3 = conv_w[3 * 128 + (tid & 127)];
    const float cb  = conv_b[tid & 127];

    auto prefetch = [&](int tile) {
        const int b = tile / NCH;
        const int l0 = (tile - b * NCH) * 64;
        const long base = (long)b * L_ + l0 - 1;
        for (int i = tid; i < 67 * 16; i += 512) {
            int r = i >> 4, q = i & 15;
            long gl = base + r;
            if (gl < 0) gl = 0;
            if (gl > (long)B_ * L_ - 1) gl = (long)B_ * L_ - 1;
            CP_ASYNC16(smb + P1_XB + (u32)(r * 64 + q * 4) * 4, x + gl * C_ + q * 4);
        }
    };
    auto convert = [&](int tile, int abuf) {
        const int b = tile / NCH;
        const int l0 = (tile - b * NCH) * 64;
        const float* xb = reinterpret_cast<const float*>(sm + P1_XB);
        const u32 aOff = (u32)P1_A + (u32)abuf * 24576;
        for (int i = tid; i < 67 * 16; i += 512) {
            int r = i >> 4, q = i & 15;
            int l = l0 - 1 + r;
            float4 v = *reinterpret_cast<const float4*>(xb + r * 64 + q * 4);
            if (l < 0 || l >= L_) v = make_float4(0.f, 0.f, 0.f, 0.f);
            u16 h0,lo0,h1,lo1,h2,lo2,h3,lo3;
            bf16_split(v.x, h0, lo0); bf16_split(v.y, h1, lo1);
            bf16_split(v.z, h2, lo2); bf16_split(v.w, h3, lo3);
            ull hv = (ull)h0 | ((ull)h1 << 16) | ((ull)h2 << 32) | ((ull)h3 << 48);
            ull lv = (ull)lo0 | ((ull)lo1 << 16) | ((ull)lo2 << 32) | ((ull)lo3 << 48);
            u32 off = (u32)r * 128 + ((((q >> 1) ^ (r & 7))) << 4) + (q & 1) * 8;
            *reinterpret_cast<ull*>(sm + aOff + off) = hv;
            *reinterpret_cast<ull*>(sm + aOff + 12288 + off) = lv;
        }
    };

    const int tile0 = blockIdx.x;
    if (tile0 < NTIL) {
        prefetch(tile0); CP_COMMIT(); CP_WAIT(0);
        convert(tile0, 0);
    }
    __syncthreads();

    int it = 0;
    for (int tile = tile0; tile < NTIL; tile += gridDim.x, it++) {
        const int buf = it & 1;
        const int b     = tile / NCH;
        const int chunk = tile - b * NCH;
        const int l0    = chunk * 64;
        const int nxt   = tile + gridDim.x;

        if (nxt < NTIL) { prefetch(nxt); CP_COMMIT(); }

        const int w = tid >> 5, lane = tid & 31;
        const int wm = w >> 3;
        const int wn = w & 7;

        float acc[3][4][4];
        #pragma unroll
        for (int mf = 0; mf < 3; mf++)
            #pragma unroll
            for (int nf = 0; nf < 4; nf++)
                #pragma unroll
                for (int j = 0; j < 4; j++) acc[mf][nf][j] = 0.f;

        const u32 aHb = smb + P1_A + (u32)buf * 24576;
        const u32 aLb = aHb + 12288;
        const u32 bHb = smb + P1_W1H, bLb = smb + P1_W1L;

        #pragma unroll
        for (int ks = 0; ks < 4; ks++) {
            u32 ah[3][4], al[3][4];
            #pragma unroll
            for (int mf = 0; mf < 3; mf++) {
                int row = wm * 48 + mf * 16 + (lane & 15);
                int ck  = ks * 2 + (lane >> 4);
                u32 off = (u32)row * 128 + (((ck ^ (row & 7))) << 4);
                ldmatrix_x4(ah[mf][0], ah[mf][1], ah[mf][2], ah[mf][3], aHb + off);
                ldmatrix_x4(al[mf][0], al[mf][1], al[mf][2], al[mf][3], aLb + off);
            }
            int krow = ks * 16 + (lane & 15);
            u32 krbase = (u32)krow * 512;
            int kx = krow & 7;
            #pragma unroll
            for (int nf = 0; nf < 4; nf++) {
                int n0 = wn * 32 + nf * 8;
                u32 off = krbase + ((((n0 >> 3) ^ kx)) << 4);
                u32 bh0, bh1, bl0, bl1;
                ldmatrix_x2t(bh0, bh1, bHb + off);
                ldmatrix_x2t(bl0, bl1, bLb + off);
                #pragma unroll
                for (int mf = 0; mf < 3; mf++) {
                    mma_bf16(acc[mf][nf][0], acc[mf][nf][1], acc[mf][nf][2], acc[mf][nf][3],
                             ah[mf][0], ah[mf][1], ah[mf][2], ah[mf][3], bh0, bh1);
                    mma_bf16(acc[mf][nf][0], acc[mf][nf][1], acc[mf][nf][2], acc[mf][nf][3],
                             ah[mf][0], ah[mf][1], ah[mf][2], ah[mf][3], bl0, bl1);
                    mma_bf16(acc[mf][nf][0], acc[mf][nf][1], acc[mf][nf][2], acc[mf][nf][3],
                             al[mf][0], al[mf][1], al[mf][2], al[mf][3], bh0, bh1);
                }
            }
        }

        if (nxt < NTIL) CP_WAIT(0);

        #pragma unroll
        for (int mf = 0; mf < 3; mf++) {
            const int r0 = wm * 48 + mf * 16 + (lane >> 2);
            #pragma unroll
            for (int nf = 0; nf < 4; nf++) {
                const int n = wn * 32 + nf * 8 + (lane & 3) * 2;
                if (wn < 4) {
                    if (r0 < 67)
                        *reinterpret_cast<float2*>(s_xs + r0 * 130 + n) =
                            make_float2(acc[mf][nf][0], acc[mf][nf][1]);
                    if (r0 + 8 < 67)
                        *reinterpret_cast<float2*>(s_xs + (r0 + 8) * 130 + n) =
                            make_float2(acc[mf][nf][2], acc[mf][nf][3]);
                } else {
                    const int nn = n - 128;
                    if (r0 >= 1 && r0 <= 64) {
                        float v0 = acc[mf][nf][0], v1 = acc[mf][nf][1];
                        *reinterpret_cast<float2*>(
                            g_res + ((size_t)b * L_ + l0 + r0 - 1) * DI_ + nn) =
                            make_float2(v0 / (1.f + __expf(-v0)), v1 / (1.f + __expf(-v1)));
                    }
                    const int r1 = r0 + 8;
                    if (r1 >= 1 && r1 <= 64) {
                        float v0 = acc[mf][nf][2], v1 = acc[mf][nf][3];
                        *reinterpret_cast<float2*>(
                            g_res + ((size_t)b * L_ + l0 + r1 - 1) * DI_ + nn) =
                            make_float2(v0 / (1.f + __expf(-v0)), v1 / (1.f + __expf(-v1)));
                    }
                }
            }
        }
        if (nxt < NTIL) convert(nxt, buf ^ 1);
        __syncthreads();

        {
            u16* imgh = reinterpret_cast<u16*>(sm + P1_XCH);
            u16* imgl = reinterpret_cast<u16*>(sm + P1_XCL);
            const int cch = tid & 127, qtr = tid >> 7;
            const int t0 = qtr * 16;
            float v0 = s_xs[(t0 + 0) * 130 + cch];
            float v1 = s_xs[(t0 + 1) * 130 + cch];
            float v2 = s_xs[(t0 + 2) * 130 + cch];
            #pragma unroll 4
            for (int t = t0; t < t0 + 16; t++) {
                float v3 = s_xs[(t + 3) * 130 + cch];
                float z = fmaf(cw0, v0, fmaf(cw1, v1, fmaf(cw2, v2, fmaf(cw3, v3, cb))));
                float sig = 1.f / (1.f + __expf(-z));
                float v = z * sig;
                u16 h, l; bf16_split(v, h, l);
                u32 off = (u32)t * 256 + ((((cch >> 3) ^ (t & 7))) << 4) + (cch & 7) * 2;
                imgh[off >> 1] = h; imgl[off >> 1] = l;
                v0 = v1; v1 = v2; v2 = v3;
            }
        }
        __syncthreads();

        {
            const uint4* sh = reinterpret_cast<const uint4*>(sm + P1_XCH);
            const uint4* sl = reinterpret_cast<const uint4*>(sm + P1_XCL);
            for (int i = tid; i < 1024; i += 512) {
                g_xch4[(size_t)tile * 1024 + i] = sh[i];
                g_xcl4[(size_t)tile * 1024 + i] = sl[i];
            }
        }
    }
}

// =====================================================================
// kb: persistent tensor GEMM2 (R10 structure, ks loop fully unrolled)
// =====================================================================
__global__ __launch_bounds__(512, 1)
void kb_kernel(const float* __restrict__ b_dt)
{
    extern __shared__ char sm[];
    const u32 smb = smem_u32(sm);
    float* s_bdt  = reinterpret_cast<float*>(sm + KB_BDT);
    float* s_sums = reinterpret_cast<float*>(sm + KB_SUMS);

    const int tid  = threadIdx.x;
    const int w    = tid >> 5;
    const int lane = tid & 31;
    const int wm   = w >> 3;        // 0..1 : rows [wm*32, +32)
    const int wg   = w & 7;         // 0..7 : xp cols [wg*16,+16), dt +128

    {
        uint4* dh = reinterpret_cast<uint4*>(sm + KB_BH);
        uint4* dl = reinterpret_cast<uint4*>(sm + KB_BL);
        for (int i = tid; i < 4096; i += 512) { dh[i] = g_Bh4[i]; dl[i] = g_Bl4[i]; }
    }
    if (tid < 128) { s_bdt[tid] = b_dt[tid]; s_sums[tid] = 0.f; }

    int tile0 = blockIdx.x;
    if (tile0 < NTIL) {
        u32 dh = smb + KB_A;
        const char* srcH = reinterpret_cast<const char*>(g_xch4 + (size_t)tile0 * 1024);
        const char* srcL = reinterpret_cast<const char*>(g_xcl4 + (size_t)tile0 * 1024);
        for (int i = tid; i < 1024; i += 512) {
            CP_ASYNC16(dh + i * 16,         srcH + i * 16);
            CP_ASYNC16(dh + 16384 + i * 16, srcL + i * 16);
        }
    }
    CP_COMMIT();

    int it = 0;
    for (int tile = tile0; tile < NTIL; tile += gridDim.x, it++) {
        const int buf = it & 1;
        const int nxt = tile + gridDim.x;
        if (nxt < NTIL) {
            u32 dh = smb + KB_A + (buf ^ 1) * 32768;
            const char* srcH = reinterpret_cast<const char*>(g_xch4 + (size_t)nxt * 1024);
            const char* srcL = reinterpret_cast<const char*>(g_xcl4 + (size_t)nxt * 1024);
            for (int i = tid; i < 1024; i += 512) {
                CP_ASYNC16(dh + i * 16,         srcH + i * 16);
                CP_ASYNC16(dh + 16384 + i * 16, srcL + i * 16);
            }
            CP_COMMIT();
            CP_WAIT(1);
        } else {
            CP_WAIT(0);
        }
        __syncthreads();

        const u32 aH = smb + KB_A + buf * 32768;
        const u32 aL = aH + 16384;
        const u32 bH = smb + KB_BH;
        const u32 bL = smb + KB_BL;

        float acc[2][4][4];
        #pragma unroll
        for (int mf = 0; mf < 2; mf++)
            #pragma unroll
            for (int nf = 0; nf < 4; nf++)
                #pragma unroll
                for (int j = 0; j < 4; j++) acc[mf][nf][j] = 0.f;

        #pragma unroll
        for (int ks = 0; ks < 8; ks++) {
            u32 ah[2][4], al[2][4];
            #pragma unroll
            for (int mf = 0; mf < 2; mf++) {
                int row = wm * 32 + mf * 16 + (lane & 15);
                int ck = ks * 2 + (lane >> 4);
                u32 off = (u32)row * 256 + (((ck ^ (row & 7))) << 4);
                ldmatrix_x4(ah[mf][0], ah[mf][1], ah[mf][2], ah[mf][3], aH + off);
                ldmatrix_x4(al[mf][0], al[mf][1], al[mf][2], al[mf][3], aL + off);
            }
            int krow = ks * 16 + (lane & 15);
            u32 krbase = (u32)krow * 512;
            int kx = krow & 7;
            #pragma unroll
            for (int nfi = 0; nfi < 4; nfi++) {
                int n0 = (nfi < 2) ? (wg * 16 + nfi * 8) : (128 + wg * 16 + (nfi - 2) * 8);
                u32 off = krbase + ((((n0 >> 3) ^ kx)) << 4);
                u32 bh0, bh1, bl0, bl1;
                ldmatrix_x2t(bh0, bh1, bH + off);
                ldmatrix_x2t(bl0, bl1, bL + off);
                #pragma unroll
                for (int mf = 0; mf < 2; mf++) {
                    mma_bf16(acc[mf][nfi][0], acc[mf][nfi][1], acc[mf][nfi][2], acc[mf][nfi][3],
                             ah[mf][0], ah[mf][1], ah[mf][2], ah[mf][3], bh0, bh1);
                    mma_bf16(acc[mf][nfi][0], acc[mf][nfi][1], acc[mf][nfi][2], acc[mf][nfi][3],
                             ah[mf][0], ah[mf][1], ah[mf][2], ah[mf][3], bl0, bl1);
                    mma_bf16(acc[mf][nfi][0], acc[mf][nfi][1], acc[mf][nfi][2], acc[mf][nfi][3],
                             al[mf][0], al[mf][1], al[mf][2], al[mf][3], bh0, bh1);
                }
            }
        }

        #pragma unroll
        for (int mf = 0; mf < 2; mf++) {
            const int r0 = wm * 32 + mf * 16 + (lane >> 2);
            const size_t tok0 = (size_t)tile * 64 + r0;
            #pragma unroll
            for (int nfi = 0; nfi < 2; nfi++) {
                const int n = wg * 16 + nfi * 8 + (lane & 3) * 2;
                float bd0 = s_bdt[n], bd1 = s_bdt[n + 1];
                float u00 = acc[mf][nfi][0] * softplus_f(acc[mf][nfi + 2][0] + bd0);
                float u01 = acc[mf][nfi][1] * softplus_f(acc[mf][nfi + 2][1] + bd1);
                float u10 = acc[mf][nfi][2] * softplus_f(acc[mf][nfi + 2][2] + bd0);
                float u11 = acc[mf][nfi][3] * softplus_f(acc[mf][nfi + 2][3] + bd1);
                *reinterpret_cast<float2*>(g_u + tok0 * DI_ + n)       = make_float2(u00, u01);
                *reinterpret_cast<float2*>(g_u + (tok0 + 8) * DI_ + n) = make_float2(u10, u11);
                float p0 = u00 + u10, p1 = u01 + u11;
                #pragma unroll
                for (int m = 4; m <= 16; m <<= 1) {
                    p0 += __shfl_xor_sync(0xffffffffu, p0, m);
                    p1 += __shfl_xor_sync(0xffffffffu, p1, m);
                }
                if ((lane >> 2) == 0) {
                    atomicAdd(&s_sums[n], p0);
                    atomicAdd(&s_sums[n + 1], p1);
                }
            }
        }
        __syncthreads();
        if (tid < 128) {
            g_sums[(size_t)tile * DI_ + tid] = s_sums[tid];
            s_sums[tid] = 0.f;
        }
    }
}

// =====================================================================
// K2: exclusive scan of chunk sums
// =====================================================================
__global__ void k2_scan(void)
{
    const int b = blockIdx.x >> 7;
    const int c = blockIdx.x & 127;
    const int t = threadIdx.x;
    __shared__ float part[64];

    float local[27];
    float s = 0.f;
    #pragma unroll
    for (int i = 0; i < 27; i++) {
        local[i] = g_sums[(b * NCH + t * 27 + i) * DI_ + c];
        s += local[i];
    }
    part[t] = s;
    __syncthreads();
    if (t == 0) {
        float run = 0.f;
        for (int i = 0; i < 64; i++) { float v = part[i]; part[i] = run; run += v; }
    }
    __syncthreads();
    float run = part[t];
    #pragma unroll
    for (int i = 0; i < 27; i++) {
        g_offs[(b * NCH + t * 27 + i) * DI_ + c] = run;
        run += local[i];
    }
}

// =====================================================================
// K3: PERSISTENT scan -> y images ; tensor y@W_out ; +x ; LayerNorm
// =====================================================================
__global__ __launch_bounds__(256, 3)
void k3_kernel(const float* __restrict__ x,
               const float* __restrict__ gamma,
               const float* __restrict__ beta,
               float* __restrict__ out)
{
    extern __shared__ char sm[];
    const u32 smb = smem_u32(sm);
    float* s_off = reinterpret_cast<float*>(sm + S3_OFF);
    float* s_mid = reinterpret_cast<float*>(sm + S3_MID);
    float* s_rs  = reinterpret_cast<float*>(sm + S3_RS);
    float* s_rq  = reinterpret_cast<float*>(sm + S3_RQ);
    float* s_gb  = reinterpret_cast<float*>(sm + S3_GB);

    const int tid = threadIdx.x;

    {
        uint4* dh = reinterpret_cast<uint4*>(sm + S3_W3H);
        uint4* dl = reinterpret_cast<uint4*>(sm + S3_W3L);
        for (int i = tid; i < 1024; i += 256) { dh[i] = g_W3h4[i]; dl[i] = g_W3l4[i]; }
    }
    if (tid < 64)  s_gb[tid] = gamma[tid];
    else if (tid < 128) s_gb[tid] = beta[tid - 64];

    for (int tile = blockIdx.x; tile < NTIL; tile += gridDim.x) {
        const int b     = tile / NCH;
        const int chunk = tile - b * NCH;
        const int l0    = chunk * 64;

        if (tid < 128) s_off[tid] = g_offs[(size_t)tile * DI_ + tid];
        __syncthreads();

        {
            u16* imgYH = reinterpret_cast<u16*>(sm + S3_YH);
            u16* imgYL = reinterpret_cast<u16*>(sm + S3_YL);
            const int c = tid & 127, h = tid >> 7;
            const size_t base = ((size_t)b * L_ + l0 + h * 32) * DI_ + c;
            float uv[32];
            #pragma unroll
            for (int i = 0; i < 32; i++) uv[i] = g_u[base + (size_t)i * DI_];
            float ps = 0.f;
            #pragma unroll
            for (int i = 0; i < 32; i++) ps += uv[i];
            if (h == 0) s_mid[c] = ps;
            __syncthreads();
            float run = s_off[c] + (h ? s_mid[c] : 0.f);
            #pragma unroll
            for (int i = 0; i < 32; i++) {
                run += uv[i];
                float r = g_res[base + (size_t)i * DI_];
                float y = run * r;
                u16 hh, ll; bf16_split(y, hh, ll);
                int t = h * 32 + i;
                u32 off = (u32)t * 256 + ((((c >> 3) ^ (t & 7))) << 4) + (c & 7) * 2;
                imgYH[off >> 1] = hh;
                imgYL[off >> 1] = ll;
            }
        }
        __syncthreads();

        {
            const int w = tid >> 5, lane = tid & 31;
            const int wm = w >> 1;
            const int wn = w & 1;

            float acc[4][4];
            #pragma unroll
            for (int nf = 0; nf < 4; nf++)
                #pragma unroll
                for (int j = 0; j < 4; j++) acc[nf][j] = 0.f;

            const u32 yHb = smb + S3_YH, yLb = smb + S3_YL;
            const u32 wHb = smb + S3_W3H, wLb = smb + S3_W3L;

            #pragma unroll
            for (int ks = 0; ks < 8; ks++) {
                u32 ah[4], al[4];
                {
                    int row = wm * 16 + (lane & 15);
                    int ck = ks * 2 + (lane >> 4);
                    u32 off = (u32)row * 256 + (((ck ^ (row & 7))) << 4);
                    ldmatrix_x4(ah[0], ah[1], ah[2], ah[3], yHb + off);
                    ldmatrix_x4(al[0], al[1], al[2], al[3], yLb + off);
                }
                int krow = ks * 16 + (lane & 15);
                u32 krbase = (u32)krow * 128;
                int kx = krow & 7;
                #pragma unroll
                for (int nf = 0; nf < 4; nf++) {
                    int n0 = wn * 32 + nf * 8;
                    u32 off = krbase + ((((n0 >> 3) ^ kx)) << 4);
                    u32 bh0, bh1, bl0, bl1;
                    ldmatrix_x2t(bh0, bh1, wHb + off);
                    ldmatrix_x2t(bl0, bl1, wLb + off);
                    mma_bf16(acc[nf][0], acc[nf][1], acc[nf][2], acc[nf][3],
                             ah[0], ah[1], ah[2], ah[3], bh0, bh1);
                    mma_bf16(acc[nf][0], acc[nf][1], acc[nf][2], acc[nf][3],
                             ah[0], ah[1], ah[2], ah[3], bl0, bl1);
                    mma_bf16(acc[nf][0], acc[nf][1], acc[nf][2], acc[nf][3],
                             al[0], al[1], al[2], al[3], bh0, bh1);
                }
            }

            const int r0 = wm * 16 + (lane >> 2);
            const int r1 = r0 + 8;
            float z[4][4];
            float s0 = 0.f, q0 = 0.f, s1 = 0.f, q1 = 0.f;
            #pragma unroll
            for (int nf = 0; nf < 4; nf++) {
                const int c0 = wn * 32 + nf * 8 + (lane & 3) * 2;
                float2 x0 = *reinterpret_cast<const float2*>(x + ((size_t)b * L_ + l0 + r0) * C_ + c0);
                float2 x1 = *reinterpret_cast<const float2*>(x + ((size_t)b * L_ + l0 + r1) * C_ + c0);
                z[nf][0] = acc[nf][0] + x0.x;
                z[nf][1] = acc[nf][1] + x0.y;
                z[nf][2] = acc[nf][2] + x1.x;
                z[nf][3] = acc[nf][3] + x1.y;
                s0 += z[nf][0] + z[nf][1];
                q0 += z[nf][0] * z[nf][0] + z[nf][1] * z[nf][1];
                s1 += z[nf][2] + z[nf][3];
                q1 += z[nf][2] * z[nf][2] + z[nf][3] * z[nf][3];
            }
            #pragma unroll
            for (int m = 1; m <= 2; m <<= 1) {
                s0 += __shfl_xor_sync(0xffffffffu, s0, m);
                q0 += __shfl_xor_sync(0xffffffffu, q0, m);
                s1 += __shfl_xor_sync(0xffffffffu, s1, m);
                q1 += __shfl_xor_sync(0xffffffffu, q1, m);
            }
            if ((lane & 3) == 0) {
                s_rs[r0 * 2 + wn] = s0; s_rq[r0 * 2 + wn] = q0;
                s_rs[r1 * 2 + wn] = s1; s_rq[r1 * 2 + wn] = q1;
            }
            __syncthreads();

            float su0 = s_rs[r0 * 2] + s_rs[r0 * 2 + 1];
            float qu0 = s_rq[r0 * 2] + s_rq[r0 * 2 + 1];
            float su1 = s_rs[r1 * 2] + s_rs[r1 * 2 + 1];
            float qu1 = s_rq[r1 * 2] + s_rq[r1 * 2 + 1];
            float mu0 = su0 * (1.f / 64.f);
            float inv0 = rsqrtf(qu0 * (1.f / 64.f) - mu0 * mu0 + EPS_);
            float mu1 = su1 * (1.f / 64.f);
            float inv1 = rsqrtf(qu1 * (1.f / 64.f) - mu1 * mu1 + EPS_);

            #pragma unroll
            for (int nf = 0; nf < 4; nf++) {
                const int c0 = wn * 32 + nf * 8 + (lane & 3) * 2;
                float g0 = s_gb[c0], g1 = s_gb[c0 + 1];
                float be0 = s_gb[64 + c0], be1 = s_gb[64 + c0 + 1];
                *reinterpret_cast<float2*>(out + ((size_t)b * L_ + l0 + r0) * C_ + c0) =
                    make_float2(fmaf(g0, (z[nf][0] - mu0) * inv0, be0),
                                fmaf(g1, (z[nf][1] - mu0) * inv0, be1));
                *reinterpret_cast<float2*>(out + ((size_t)b * L_ + l0 + r1) * C_ + c0) =
                    make_float2(fmaf(g0, (z[nf][2] - mu1) * inv1, be0),
                                fmaf(g1, (z[nf][3] - mu1) * inv1, be1));
            }
        }
        __syncthreads();
    }
}

// =====================================================================
extern "C" void kernel_launch(void* const* d_in, const int* in_sizes, int n_in,
                              void* d_out, int out_size)
{
    (void)in_sizes; (void)n_in; (void)out_size;
    const float* x      = (const float*)d_in[0];
    const float* W_in   = (const float*)d_in[1];
    const float* conv_w = (const float*)d_in[2];
    const float* conv_b = (const float*)d_in[3];
    const float* W_x    = (const float*)d_in[4];
    const float* W_dt   = (const float*)d_in[5];
    const float* b_dt   = (const float*)d_in[6];
    const float* W_out  = (const float*)d_in[7];
    const float* gamma  = (const float*)d_in[8];
    const float* beta   = (const float*)d_in[9];
    float* out = (float*)d_out;

    cudaFuncSetAttribute(k1a_kernel, cudaFuncAttributeMaxDynamicSharedMemorySize, P1_SMEM);
    cudaFuncSetAttribute(kb_kernel,  cudaFuncAttributeMaxDynamicSharedMemorySize, KB_SMEM);
    cudaFuncSetAttribute(k3_kernel,  cudaFuncAttributeMaxDynamicSharedMemorySize, S3_SMEM);

    // launch order: profiled global launch idx 3 == kb
    k_prep_w2<<<16, 256>>>(W_x, W_dt);                      // 0
    k_prep_w13<<<16, 256>>>(W_in, W_out);                   // 1
    k1a_kernel<<<148, 512, P1_SMEM>>>(x, conv_w, conv_b);   // 2
    kb_kernel<<<148, 512, KB_SMEM>>>(b_dt);                 // 3 <- profiled
    k2_scan<<<B_ * 128, 64>>>();                            // 4
    k3_kernel<<<444, 256, S3_SMEM>>>(x, gamma, beta, out);  // 5
}

// round 15
// speedup vs baseline: 1.4162x; 1.0166x over previous
#include <cuda_runtime.h>
#include <cuda_bf16.h>
#include <cstdint>

typedef unsigned long long ull;
typedef unsigned int u32;
typedef unsigned short u16;

#define B_   2
#define L_   110592
#define C_   64
#define DI_  128
#define NCH  1728
#define NTIL (B_ * NCH)         // 3456
#define EPS_ 1e-3f

// ---- k1a smem layout v3 (bytes) ----
#define P1_W1H 0
#define P1_W1L 32768
#define P1_XB  65536
#define P1_A   82944
#define P1_XS  132096
#define P1_XCH 167936
#define P1_XCL 184320
#define P1_SMEM 200704
// ---- kb smem layout (bytes) ----
#define KB_BH   0
#define KB_BL   65536
#define KB_A    131072          // 2 x 32KB
#define KB_BDT  196608
#define KB_SUMS 197120
#define KB_SMEM 197632
// ---- k3 smem layout (bytes) ----
#define S3_W3H 0
#define S3_W3L 16384
#define S3_YH  32768
#define S3_YL  49152
#define S3_OFF 65536
#define S3_MID 66048
#define S3_RS  66560
#define S3_RQ  67072
#define S3_GB  67584
#define S3_SMEM 68096

// ---------------- global scratch ----------------
__device__ float g_u[(size_t)B_ * L_ * DI_];
__device__ float g_res[(size_t)B_ * L_ * DI_];
__device__ float g_sums[NTIL * DI_];
__device__ float g_offs[NTIL * DI_];
__device__ uint4 g_xch4[(size_t)NTIL * 1024];
__device__ uint4 g_xcl4[(size_t)NTIL * 1024];
__device__ uint4 g_Bh4[4096];
__device__ uint4 g_Bl4[4096];
__device__ uint4 g_W1h4[2048];
__device__ uint4 g_W1l4[2048];
__device__ uint4 g_W3h4[1024];
__device__ uint4 g_W3l4[1024];

// ---------------- helpers ----------------
__device__ __forceinline__ float softplus_f(float v) {
    return (v > 10.f) ? v : __logf(1.f + __expf(v));
}
__device__ __forceinline__ u32 smem_u32(const void* p) {
    u32 a; asm("{ .reg .u64 t; cvta.to.shared.u64 t, %1; cvt.u32.u64 %0, t; }"
               : "=r"(a) : "l"(p));
    return a;
}
__device__ __forceinline__ void mma_bf16(float& d0, float& d1, float& d2, float& d3,
                                         u32 a0, u32 a1, u32 a2, u32 a3,
                                         u32 b0, u32 b1) {
    asm volatile("mma.sync.aligned.m16n8k16.row.col.f32.bf16.bf16.f32 "
                 "{%0,%1,%2,%3}, {%4,%5,%6,%7}, {%8,%9}, {%0,%1,%2,%3};"
                 : "+f"(d0), "+f"(d1), "+f"(d2), "+f"(d3)
                 : "r"(a0), "r"(a1), "r"(a2), "r"(a3), "r"(b0), "r"(b1));
}
__device__ __forceinline__ void ldmatrix_x4(u32& r0, u32& r1, u32& r2, u32& r3, u32 addr) {
    asm volatile("ldmatrix.sync.aligned.m8n8.x4.shared.b16 {%0,%1,%2,%3}, [%4];"
                 : "=r"(r0), "=r"(r1), "=r"(r2), "=r"(r3) : "r"(addr));
}
__device__ __forceinline__ void ldmatrix_x2t(u32& r0, u32& r1, u32 addr) {
    asm volatile("ldmatrix.sync.aligned.m8n8.x2.trans.shared.b16 {%0,%1}, [%2];"
                 : "=r"(r0), "=r"(r1) : "r"(addr));
}
#define CP_ASYNC16(dst, src) \
    asm volatile("cp.async.cg.shared.global [%0], [%1], 16;" :: "r"(dst), "l"(src))
#define CP_COMMIT() asm volatile("cp.async.commit_group;")
#define CP_WAIT(n)  asm volatile("cp.async.wait_group %0;" :: "n"(n))

// Truncation split: v = hi + lo EXACTLY.
__device__ __forceinline__ void bf16_split(float v, u16& h, u16& l) {
    u32 bits = __float_as_uint(v);
    h = (u16)(bits >> 16);
    float hf = __uint_as_float(bits & 0xFFFF0000u);
    __nv_bfloat16 lb = __float2bfloat16(v - hf);
    l = *reinterpret_cast<u16*>(&lb);
}

// =====================================================================
// k_prep_all: all weight images in one launch
// =====================================================================
__global__ void k_prep_all(const float* __restrict__ W_x,
                           const float* __restrict__ W_dt,
                           const float* __restrict__ W_in,
                           const float* __restrict__ W_out)
{
    u16* bh = reinterpret_cast<u16*>(g_Bh4);
    u16* bl = reinterpret_cast<u16*>(g_Bl4);
    u16* wh = reinterpret_cast<u16*>(g_W1h4);
    u16* wl = reinterpret_cast<u16*>(g_W1l4);
    u16* oh = reinterpret_cast<u16*>(g_W3h4);
    u16* ol = reinterpret_cast<u16*>(g_W3l4);
    int idx = blockIdx.x * 256 + threadIdx.x;
    for (int i = idx; i < 128 * 256; i += gridDim.x * 256) {
        int k = i >> 8, n = i & 255;
        float w = (n < 128) ? W_x[(size_t)k * 144 + n] : W_dt[(size_t)k * 128 + (n - 128)];
        u16 h, l; bf16_split(w, h, l);
        u32 off = (u32)k * 512 + ((((n >> 3) ^ (k & 7))) << 4) + (n & 7) * 2;
        bh[off >> 1] = h; bl[off >> 1] = l;
    }
    for (int i = idx; i < 64 * 256; i += gridDim.x * 256) {
        int k = i >> 8, n = i & 255;
        float w = W_in[(size_t)k * 256 + n];
        u16 h, l; bf16_split(w, h, l);
        u32 off = (u32)k * 512 + ((((n >> 3) ^ (k & 7))) << 4) + (n & 7) * 2;
        wh[off >> 1] = h; wl[off >> 1] = l;
    }
    for (int i = idx; i < 128 * 64; i += gridDim.x * 256) {
        int k = i >> 6, n = i & 63;
        float w = W_out[(size_t)k * 64 + n];
        u16 h, l; bf16_split(w, h, l);
        u32 off = (u32)k * 128 + ((((n >> 3) ^ (k & 7))) << 4) + (n & 7) * 2;
        oh[off >> 1] = h; ol[off >> 1] = l;
    }
}

// =====================================================================
// k1a v3: PERSISTENT (exact R10)
// =====================================================================
__global__ __launch_bounds__(512, 1)
void k1a_kernel(const float* __restrict__ x,
                const float* __restrict__ conv_w,
                const float* __restrict__ conv_b)
{
    extern __shared__ char sm[];
    const u32 smb = smem_u32(sm);
    float* s_xs = reinterpret_cast<float*>(sm + P1_XS);

    const int tid = threadIdx.x;

    {
        uint4* dh = reinterpret_cast<uint4*>(sm + P1_W1H);
        uint4* dl = reinterpret_cast<uint4*>(sm + P1_W1L);
        for (int i = tid; i < 2048; i += 512) { dh[i] = g_W1h4[i]; dl[i] = g_W1l4[i]; }
    }
    const float cw0 = conv_w[0 * 128 + (tid & 127)];
    const float cw1 = conv_w[1 * 128 + (tid & 127)];
    const float cw2 = conv_w[2 * 128 + (tid & 127)];
    const float cw3 = conv_w[3 * 128 + (tid & 127)];
    const float cb  = conv_b[tid & 127];

    auto prefetch = [&](int tile) {
        const int b = tile / NCH;
        const int l0 = (tile - b * NCH) * 64;
        const long base = (long)b * L_ + l0 - 1;
        for (int i = tid; i < 67 * 16; i += 512) {
            int r = i >> 4, q = i & 15;
            long gl = base + r;
            if (gl < 0) gl = 0;
            if (gl > (long)B_ * L_ - 1) gl = (long)B_ * L_ - 1;
            CP_ASYNC16(smb + P1_XB + (u32)(r * 64 + q * 4) * 4, x + gl * C_ + q * 4);
        }
    };
    auto convert = [&](int tile, int abuf) {
        const int b = tile / NCH;
        const int l0 = (tile - b * NCH) * 64;
        const float* xb = reinterpret_cast<const float*>(sm + P1_XB);
        const u32 aOff = (u32)P1_A + (u32)abuf * 24576;
        for (int i = tid; i < 67 * 16; i += 512) {
            int r = i >> 4, q = i & 15;
            int l = l0 - 1 + r;
            float4 v = *reinterpret_cast<const float4*>(xb + r * 64 + q * 4);
            if (l < 0 || l >= L_) v = make_float4(0.f, 0.f, 0.f, 0.f);
            u16 h0,lo0,h1,lo1,h2,lo2,h3,lo3;
            bf16_split(v.x, h0, lo0); bf16_split(v.y, h1, lo1);
            bf16_split(v.z, h2, lo2); bf16_split(v.w, h3, lo3);
            ull hv = (ull)h0 | ((ull)h1 << 16) | ((ull)h2 << 32) | ((ull)h3 << 48);
            ull lv = (ull)lo0 | ((ull)lo1 << 16) | ((ull)lo2 << 32) | ((ull)lo3 << 48);
            u32 off = (u32)r * 128 + ((((q >> 1) ^ (r & 7))) << 4) + (q & 1) * 8;
            *reinterpret_cast<ull*>(sm + aOff + off) = hv;
            *reinterpret_cast<ull*>(sm + aOff + 12288 + off) = lv;
        }
    };

    const int tile0 = blockIdx.x;
    if (tile0 < NTIL) {
        prefetch(tile0); CP_COMMIT(); CP_WAIT(0);
        convert(tile0, 0);
    }
    __syncthreads();

    int it = 0;
    for (int tile = tile0; tile < NTIL; tile += gridDim.x, it++) {
        const int buf = it & 1;
        const int b     = tile / NCH;
        const int chunk = tile - b * NCH;
        const int l0    = chunk * 64;
        const int nxt   = tile + gridDim.x;

        if (nxt < NTIL) { prefetch(nxt); CP_COMMIT(); }

        const int w = tid >> 5, lane = tid & 31;
        const int wm = w >> 3;
        const int wn = w & 7;

        float acc[3][4][4];
        #pragma unroll
        for (int mf = 0; mf < 3; mf++)
            #pragma unroll
            for (int nf = 0; nf < 4; nf++)
                #pragma unroll
                for (int j = 0; j < 4; j++) acc[mf][nf][j] = 0.f;

        const u32 aHb = smb + P1_A + (u32)buf * 24576;
        const u32 aLb = aHb + 12288;
        const u32 bHb = smb + P1_W1H, bLb = smb + P1_W1L;

        #pragma unroll
        for (int ks = 0; ks < 4; ks++) {
            u32 ah[3][4], al[3][4];
            #pragma unroll
            for (int mf = 0; mf < 3; mf++) {
                int row = wm * 48 + mf * 16 + (lane & 15);
                int ck  = ks * 2 + (lane >> 4);
                u32 off = (u32)row * 128 + (((ck ^ (row & 7))) << 4);
                ldmatrix_x4(ah[mf][0], ah[mf][1], ah[mf][2], ah[mf][3], aHb + off);
                ldmatrix_x4(al[mf][0], al[mf][1], al[mf][2], al[mf][3], aLb + off);
            }
            int krow = ks * 16 + (lane & 15);
            u32 krbase = (u32)krow * 512;
            int kx = krow & 7;
            #pragma unroll
            for (int nf = 0; nf < 4; nf++) {
                int n0 = wn * 32 + nf * 8;
                u32 off = krbase + ((((n0 >> 3) ^ kx)) << 4);
                u32 bh0, bh1, bl0, bl1;
                ldmatrix_x2t(bh0, bh1, bHb + off);
                ldmatrix_x2t(bl0, bl1, bLb + off);
                #pragma unroll
                for (int mf = 0; mf < 3; mf++) {
                    mma_bf16(acc[mf][nf][0], acc[mf][nf][1], acc[mf][nf][2], acc[mf][nf][3],
                             ah[mf][0], ah[mf][1], ah[mf][2], ah[mf][3], bh0, bh1);
                    mma_bf16(acc[mf][nf][0], acc[mf][nf][1], acc[mf][nf][2], acc[mf][nf][3],
                             ah[mf][0], ah[mf][1], ah[mf][2], ah[mf][3], bl0, bl1);
                    mma_bf16(acc[mf][nf][0], acc[mf][nf][1], acc[mf][nf][2], acc[mf][nf][3],
                             al[mf][0], al[mf][1], al[mf][2], al[mf][3], bh0, bh1);
                }
            }
        }

        if (nxt < NTIL) CP_WAIT(0);

        #pragma unroll
        for (int mf = 0; mf < 3; mf++) {
            const int r0 = wm * 48 + mf * 16 + (lane >> 2);
            #pragma unroll
            for (int nf = 0; nf < 4; nf++) {
                const int n = wn * 32 + nf * 8 + (lane & 3) * 2;
                if (wn < 4) {
                    if (r0 < 67)
                        *reinterpret_cast<float2*>(s_xs + r0 * 130 + n) =
                            make_float2(acc[mf][nf][0], acc[mf][nf][1]);
                    if (r0 + 8 < 67)
                        *reinterpret_cast<float2*>(s_xs + (r0 + 8) * 130 + n) =
                            make_float2(acc[mf][nf][2], acc[mf][nf][3]);
                } else {
                    const int nn = n - 128;
                    if (r0 >= 1 && r0 <= 64) {
                        float v0 = acc[mf][nf][0], v1 = acc[mf][nf][1];
                        *reinterpret_cast<float2*>(
                            g_res + ((size_t)b * L_ + l0 + r0 - 1) * DI_ + nn) =
                            make_float2(v0 / (1.f + __expf(-v0)), v1 / (1.f + __expf(-v1)));
                    }
                    const int r1 = r0 + 8;
                    if (r1 >= 1 && r1 <= 64) {
                        float v0 = acc[mf][nf][2], v1 = acc[mf][nf][3];
                        *reinterpret_cast<float2*>(
                            g_res + ((size_t)b * L_ + l0 + r1 - 1) * DI_ + nn) =
                            make_float2(v0 / (1.f + __expf(-v0)), v1 / (1.f + __expf(-v1)));
                    }
                }
            }
        }
        if (nxt < NTIL) convert(nxt, buf ^ 1);
        __syncthreads();

        {
            u16* imgh = reinterpret_cast<u16*>(sm + P1_XCH);
            u16* imgl = reinterpret_cast<u16*>(sm + P1_XCL);
            const int cch = tid & 127, qtr = tid >> 7;
            const int t0 = qtr * 16;
            float v0 = s_xs[(t0 + 0) * 130 + cch];
            float v1 = s_xs[(t0 + 1) * 130 + cch];
            float v2 = s_xs[(t0 + 2) * 130 + cch];
            #pragma unroll 4
            for (int t = t0; t < t0 + 16; t++) {
                float v3 = s_xs[(t + 3) * 130 + cch];
                float z = fmaf(cw0, v0, fmaf(cw1, v1, fmaf(cw2, v2, fmaf(cw3, v3, cb))));
                float sig = 1.f / (1.f + __expf(-z));
                float v = z * sig;
                u16 h, l; bf16_split(v, h, l);
                u32 off = (u32)t * 256 + ((((cch >> 3) ^ (t & 7))) << 4) + (cch & 7) * 2;
                imgh[off >> 1] = h; imgl[off >> 1] = l;
                v0 = v1; v1 = v2; v2 = v3;
            }
        }
        __syncthreads();

        {
            const uint4* sh = reinterpret_cast<const uint4*>(sm + P1_XCH);
            const uint4* sl = reinterpret_cast<const uint4*>(sm + P1_XCL);
            for (int i = tid; i < 1024; i += 512) {
                g_xch4[(size_t)tile * 1024 + i] = sh[i];
                g_xcl4[(size_t)tile * 1024 + i] = sl[i];
            }
        }
    }
}

// =====================================================================
// kb: persistent tensor GEMM2 (exact R10: rolled ks loop)
// =====================================================================
__global__ __launch_bounds__(512, 1)
void kb_kernel(const float* __restrict__ b_dt)
{
    extern __shared__ char sm[];
    const u32 smb = smem_u32(sm);
    float* s_bdt  = reinterpret_cast<float*>(sm + KB_BDT);
    float* s_sums = reinterpret_cast<float*>(sm + KB_SUMS);

    const int tid  = threadIdx.x;
    const int w    = tid >> 5;
    const int lane = tid & 31;
    const int wm   = w >> 3;        // 0..1 : rows [wm*32, +32)
    const int wg   = w & 7;         // 0..7 : xp cols [wg*16,+16), dt +128

    {
        uint4* dh = reinterpret_cast<uint4*>(sm + KB_BH);
        uint4* dl = reinterpret_cast<uint4*>(sm + KB_BL);
        for (int i = tid; i < 4096; i += 512) { dh[i] = g_Bh4[i]; dl[i] = g_Bl4[i]; }
    }
    if (tid < 128) { s_bdt[tid] = b_dt[tid]; s_sums[tid] = 0.f; }

    int tile0 = blockIdx.x;
    if (tile0 < NTIL) {
        u32 dh = smb + KB_A;
        const char* srcH = reinterpret_cast<const char*>(g_xch4 + (size_t)tile0 * 1024);
        const char* srcL = reinterpret_cast<const char*>(g_xcl4 + (size_t)tile0 * 1024);
        for (int i = tid; i < 1024; i += 512) {
            CP_ASYNC16(dh + i * 16,         srcH + i * 16);
            CP_ASYNC16(dh + 16384 + i * 16, srcL + i * 16);
        }
    }
    CP_COMMIT();

    int it = 0;
    for (int tile = tile0; tile < NTIL; tile += gridDim.x, it++) {
        const int buf = it & 1;
        const int nxt = tile + gridDim.x;
        if (nxt < NTIL) {
            u32 dh = smb + KB_A + (buf ^ 1) * 32768;
            const char* srcH = reinterpret_cast<const char*>(g_xch4 + (size_t)nxt * 1024);
            const char* srcL = reinterpret_cast<const char*>(g_xcl4 + (size_t)nxt * 1024);
            for (int i = tid; i < 1024; i += 512) {
                CP_ASYNC16(dh + i * 16,         srcH + i * 16);
                CP_ASYNC16(dh + 16384 + i * 16, srcL + i * 16);
            }
            CP_COMMIT();
            CP_WAIT(1);
        } else {
            CP_WAIT(0);
        }
        __syncthreads();

        const u32 aH = smb + KB_A + buf * 32768;
        const u32 aL = aH + 16384;
        const u32 bH = smb + KB_BH;
        const u32 bL = smb + KB_BL;

        float acc[2][4][4];
        #pragma unroll
        for (int mf = 0; mf < 2; mf++)
            #pragma unroll
            for (int nf = 0; nf < 4; nf++)
                #pragma unroll
                for (int j = 0; j < 4; j++) acc[mf][nf][j] = 0.f;

        #pragma unroll 1
        for (int ks = 0; ks < 8; ks++) {
            u32 ah[2][4], al[2][4];
            #pragma unroll
            for (int mf = 0; mf < 2; mf++) {
                int row = wm * 32 + mf * 16 + (lane & 15);
                int ck = ks * 2 + (lane >> 4);
                u32 off = (u32)row * 256 + (((ck ^ (row & 7))) << 4);
                ldmatrix_x4(ah[mf][0], ah[mf][1], ah[mf][2], ah[mf][3], aH + off);
                ldmatrix_x4(al[mf][0], al[mf][1], al[mf][2], al[mf][3], aL + off);
            }
            int krow = ks * 16 + (lane & 15);
            u32 krbase = (u32)krow * 512;
            int kx = krow & 7;
            #pragma unroll
            for (int nfi = 0; nfi < 4; nfi++) {
                int n0 = (nfi < 2) ? (wg * 16 + nfi * 8) : (128 + wg * 16 + (nfi - 2) * 8);
                u32 off = krbase + ((((n0 >> 3) ^ kx)) << 4);
                u32 bh0, bh1, bl0, bl1;
                ldmatrix_x2t(bh0, bh1, bH + off);
                ldmatrix_x2t(bl0, bl1, bL + off);
                #pragma unroll
                for (int mf = 0; mf < 2; mf++) {
                    mma_bf16(acc[mf][nfi][0], acc[mf][nfi][1], acc[mf][nfi][2], acc[mf][nfi][3],
                             ah[mf][0], ah[mf][1], ah[mf][2], ah[mf][3], bh0, bh1);
                    mma_bf16(acc[mf][nfi][0], acc[mf][nfi][1], acc[mf][nfi][2], acc[mf][nfi][3],
                             ah[mf][0], ah[mf][1], ah[mf][2], ah[mf][3], bl0, bl1);
                    mma_bf16(acc[mf][nfi][0], acc[mf][nfi][1], acc[mf][nfi][2], acc[mf][nfi][3],
                             al[mf][0], al[mf][1], al[mf][2], al[mf][3], bh0, bh1);
                }
            }
        }

        #pragma unroll
        for (int mf = 0; mf < 2; mf++) {
            const int r0 = wm * 32 + mf * 16 + (lane >> 2);
            const size_t tok0 = (size_t)tile * 64 + r0;
            #pragma unroll
            for (int nfi = 0; nfi < 2; nfi++) {
                const int n = wg * 16 + nfi * 8 + (lane & 3) * 2;
                float bd0 = s_bdt[n], bd1 = s_bdt[n + 1];
                float u00 = acc[mf][nfi][0] * softplus_f(acc[mf][nfi + 2][0] + bd0);
                float u01 = acc[mf][nfi][1] * softplus_f(acc[mf][nfi + 2][1] + bd1);
                float u10 = acc[mf][nfi][2] * softplus_f(acc[mf][nfi + 2][2] + bd0);
                float u11 = acc[mf][nfi][3] * softplus_f(acc[mf][nfi + 2][3] + bd1);
                *reinterpret_cast<float2*>(g_u + tok0 * DI_ + n)       = make_float2(u00, u01);
                *reinterpret_cast<float2*>(g_u + (tok0 + 8) * DI_ + n) = make_float2(u10, u11);
                float p0 = u00 + u10, p1 = u01 + u11;
                #pragma unroll
                for (int m = 4; m <= 16; m <<= 1) {
                    p0 += __shfl_xor_sync(0xffffffffu, p0, m);
                    p1 += __shfl_xor_sync(0xffffffffu, p1, m);
                }
                if ((lane >> 2) == 0) {
                    atomicAdd(&s_sums[n], p0);
                    atomicAdd(&s_sums[n + 1], p1);
                }
            }
        }
        __syncthreads();
        if (tid < 128) {
            g_sums[(size_t)tile * DI_ + tid] = s_sums[tid];
            s_sums[tid] = 0.f;
        }
    }
}

// =====================================================================
// K2: exclusive scan of chunk sums
// =====================================================================
__global__ void k2_scan(void)
{
    const int b = blockIdx.x >> 7;
    const int c = blockIdx.x & 127;
    const int t = threadIdx.x;
    __shared__ float part[64];

    float local[27];
    float s = 0.f;
    #pragma unroll
    for (int i = 0; i < 27; i++) {
        local[i] = g_sums[(b * NCH + t * 27 + i) * DI_ + c];
        s += local[i];
    }
    part[t] = s;
    __syncthreads();
    if (t == 0) {
        float run = 0.f;
        for (int i = 0; i < 64; i++) { float v = part[i]; part[i] = run; run += v; }
    }
    __syncthreads();
    float run = part[t];
    #pragma unroll
    for (int i = 0; i < 27; i++) {
        g_offs[(b * NCH + t * 27 + i) * DI_ + c] = run;
        run += local[i];
    }
}

// =====================================================================
// K3: PERSISTENT scan -> y images ; tensor y@W_out ; +x ; LayerNorm
// =====================================================================
__global__ __launch_bounds__(256, 3)
void k3_kernel(const float* __restrict__ x,
               const float* __restrict__ gamma,
               const float* __restrict__ beta,
               float* __restrict__ out)
{
    extern __shared__ char sm[];
    const u32 smb = smem_u32(sm);
    float* s_off = reinterpret_cast<float*>(sm + S3_OFF);
    float* s_mid = reinterpret_cast<float*>(sm + S3_MID);
    float* s_rs  = reinterpret_cast<float*>(sm + S3_RS);
    float* s_rq  = reinterpret_cast<float*>(sm + S3_RQ);
    float* s_gb  = reinterpret_cast<float*>(sm + S3_GB);

    const int tid = threadIdx.x;

    {
        uint4* dh = reinterpret_cast<uint4*>(sm + S3_W3H);
        uint4* dl = reinterpret_cast<uint4*>(sm + S3_W3L);
        for (int i = tid; i < 1024; i += 256) { dh[i] = g_W3h4[i]; dl[i] = g_W3l4[i]; }
    }
    if (tid < 64)  s_gb[tid] = gamma[tid];
    else if (tid < 128) s_gb[tid] = beta[tid - 64];

    for (int tile = blockIdx.x; tile < NTIL; tile += gridDim.x) {
        const int b     = tile / NCH;
        const int chunk = tile - b * NCH;
        const int l0    = chunk * 64;

        if (tid < 128) s_off[tid] = g_offs[(size_t)tile * DI_ + tid];
        __syncthreads();

        {
            u16* imgYH = reinterpret_cast<u16*>(sm + S3_YH);
            u16* imgYL = reinterpret_cast<u16*>(sm + S3_YL);
            const int c = tid & 127, h = tid >> 7;
            const size_t base = ((size_t)b * L_ + l0 + h * 32) * DI_ + c;
            float uv[32];
            #pragma unroll
            for (int i = 0; i < 32; i++) uv[i] = g_u[base + (size_t)i * DI_];
            float ps = 0.f;
            #pragma unroll
            for (int i = 0; i < 32; i++) ps += uv[i];
            if (h == 0) s_mid[c] = ps;
            __syncthreads();
            float run = s_off[c] + (h ? s_mid[c] : 0.f);
            #pragma unroll
            for (int i = 0; i < 32; i++) {
                run += uv[i];
                float r = g_res[base + (size_t)i * DI_];
                float y = run * r;
                u16 hh, ll; bf16_split(y, hh, ll);
                int t = h * 32 + i;
                u32 off = (u32)t * 256 + ((((c >> 3) ^ (t & 7))) << 4) + (c & 7) * 2;
                imgYH[off >> 1] = hh;
                imgYL[off >> 1] = ll;
            }
        }
        __syncthreads();

        {
            const int w = tid >> 5, lane = tid & 31;
            const int wm = w >> 1;
            const int wn = w & 1;

            float acc[4][4];
            #pragma unroll
            for (int nf = 0; nf < 4; nf++)
                #pragma unroll
                for (int j = 0; j < 4; j++) acc[nf][j] = 0.f;

            const u32 yHb = smb + S3_YH, yLb = smb + S3_YL;
            const u32 wHb = smb + S3_W3H, wLb = smb + S3_W3L;

            #pragma unroll
            for (int ks = 0; ks < 8; ks++) {
                u32 ah[4], al[4];
                {
                    int row = wm * 16 + (lane & 15);
                    int ck = ks * 2 + (lane >> 4);
                    u32 off = (u32)row * 256 + (((ck ^ (row & 7))) << 4);
                    ldmatrix_x4(ah[0], ah[1], ah[2], ah[3], yHb + off);
                    ldmatrix_x4(al[0], al[1], al[2], al[3], yLb + off);
                }
                int krow = ks * 16 + (lane & 15);
                u32 krbase = (u32)krow * 128;
                int kx = krow & 7;
                #pragma unroll
                for (int nf = 0; nf < 4; nf++) {
                    int n0 = wn * 32 + nf * 8;
                    u32 off = krbase + ((((n0 >> 3) ^ kx)) << 4);
                    u32 bh0, bh1, bl0, bl1;
                    ldmatrix_x2t(bh0, bh1, wHb + off);
                    ldmatrix_x2t(bl0, bl1, wLb + off);
                    mma_bf16(acc[nf][0], acc[nf][1], acc[nf][2], acc[nf][3],
                             ah[0], ah[1], ah[2], ah[3], bh0, bh1);
                    mma_bf16(acc[nf][0], acc[nf][1], acc[nf][2], acc[nf][3],
                             ah[0], ah[1], ah[2], ah[3], bl0, bl1);
                    mma_bf16(acc[nf][0], acc[nf][1], acc[nf][2], acc[nf][3],
                             al[0], al[1], al[2], al[3], bh0, bh1);
                }
            }

            const int r0 = wm * 16 + (lane >> 2);
            const int r1 = r0 + 8;
            float z[4][4];
            float s0 = 0.f, q0 = 0.f, s1 = 0.f, q1 = 0.f;
            #pragma unroll
            for (int nf = 0; nf < 4; nf++) {
                const int c0 = wn * 32 + nf * 8 + (lane & 3) * 2;
                float2 x0 = *reinterpret_cast<const float2*>(x + ((size_t)b * L_ + l0 + r0) * C_ + c0);
                float2 x1 = *reinterpret_cast<const float2*>(x + ((size_t)b * L_ + l0 + r1) * C_ + c0);
                z[nf][0] = acc[nf][0] + x0.x;
                z[nf][1] = acc[nf][1] + x0.y;
                z[nf][2] = acc[nf][2] + x1.x;
                z[nf][3] = acc[nf][3] + x1.y;
                s0 += z[nf][0] + z[nf][1];
                q0 += z[nf][0] * z[nf][0] + z[nf][1] * z[nf][1];
                s1 += z[nf][2] + z[nf][3];
                q1 += z[nf][2] * z[nf][2] + z[nf][3] * z[nf][3];
            }
            #pragma unroll
            for (int m = 1; m <= 2; m <<= 1) {
                s0 += __shfl_xor_sync(0xffffffffu, s0, m);
                q0 += __shfl_xor_sync(0xffffffffu, q0, m);
                s1 += __shfl_xor_sync(0xffffffffu, s1, m);
                q1 += __shfl_xor_sync(0xffffffffu, q1, m);
            }
            if ((lane & 3) == 0) {
                s_rs[r0 * 2 + wn] = s0; s_rq[r0 * 2 + wn] = q0;
                s_rs[r1 * 2 + wn] = s1; s_rq[r1 * 2 + wn] = q1;
            }
            __syncthreads();

            float su0 = s_rs[r0 * 2] + s_rs[r0 * 2 + 1];
            float qu0 = s_rq[r0 * 2] + s_rq[r0 * 2 + 1];
            float su1 = s_rs[r1 * 2] + s_rs[r1 * 2 + 1];
            float qu1 = s_rq[r1 * 2] + s_rq[r1 * 2 + 1];
            float mu0 = su0 * (1.f / 64.f);
            float inv0 = rsqrtf(qu0 * (1.f / 64.f) - mu0 * mu0 + EPS_);
            float mu1 = su1 * (1.f / 64.f);
            float inv1 = rsqrtf(qu1 * (1.f / 64.f) - mu1 * mu1 + EPS_);

            #pragma unroll
            for (int nf = 0; nf < 4; nf++) {
                const int c0 = wn * 32 + nf * 8 + (lane & 3) * 2;
                float g0 = s_gb[c0], g1 = s_gb[c0 + 1];
                float be0 = s_gb[64 + c0], be1 = s_gb[64 + c0 + 1];
                *reinterpret_cast<float2*>(out + ((size_t)b * L_ + l0 + r0) * C_ + c0) =
                    make_float2(fmaf(g0, (z[nf][0] - mu0) * inv0, be0),
                                fmaf(g1, (z[nf][1] - mu0) * inv0, be1));
                *reinterpret_cast<float2*>(out + ((size_t)b * L_ + l0 + r1) * C_ + c0) =
                    make_float2(fmaf(g0, (z[nf][2] - mu1) * inv1, be0),
                                fmaf(g1, (z[nf][3] - mu1) * inv1, be1));
            }
        }
        __syncthreads();
    }
}

// =====================================================================
extern "C" void kernel_launch(void* const* d_in, const int* in_sizes, int n_in,
                              void* d_out, int out_size)
{
    (void)in_sizes; (void)n_in; (void)out_size;
    const float* x      = (const float*)d_in[0];
    const float* W_in   = (const float*)d_in[1];
    const float* conv_w = (const float*)d_in[2];
    const float* conv_b = (const float*)d_in[3];
    const float* W_x    = (const float*)d_in[4];
    const float* W_dt   = (const float*)d_in[5];
    const float* b_dt   = (const float*)d_in[6];
    const float* W_out  = (const float*)d_in[7];
    const float* gamma  = (const float*)d_in[8];
    const float* beta   = (const float*)d_in[9];
    float* out = (float*)d_out;

    cudaFuncSetAttribute(k1a_kernel, cudaFuncAttributeMaxDynamicSharedMemorySize, P1_SMEM);
    cudaFuncSetAttribute(kb_kernel,  cudaFuncAttributeMaxDynamicSharedMemorySize, KB_SMEM);
    cudaFuncSetAttribute(k3_kernel,  cudaFuncAttributeMaxDynamicSharedMemorySize, S3_SMEM);

    k_prep_all<<<16, 256>>>(W_x, W_dt, W_in, W_out);        // 0
    k1a_kernel<<<148, 512, P1_SMEM>>>(x, conv_w, conv_b);   // 1
    kb_kernel<<<148, 512, KB_SMEM>>>(b_dt);                 // 2
    k2_scan<<<B_ * 128, 64>>>();                            // 3
    k3_kernel<<<444, 256, S3_SMEM>>>(x, gamma, beta, out);  // 4
}